// round 6
// baseline (speedup 1.0000x reference)
#include <cuda_runtime.h>
#include <cuda_bf16.h>
#include <cstdint>
#include <cstdio>

#define NN 50000
#define EE 800000
#define E2T (EE + NN)   // 850000 edges incl self-loops
#define IN_F 128
#define ED_F 16
#define F1 128          // HEADS*HID
#define HEADS 4
#define HID 32
#define OUTF 32
#define NEG_SLOPE 0.2f

// ---------------- scratch (device globals; no allocation allowed) ----------------
__device__ __align__(16) float g_h1[(size_t)NN * F1];     // layer1 features (pre-agg), then relu output
__device__ __align__(16) float g_acc1[(size_t)NN * F1];   // layer1 aggregation accumulator
__device__ __align__(16) float g_h2[(size_t)NN * OUTF];   // layer2 transformed features
__device__ __align__(16) float g_ex1[(size_t)E2T * HEADS];
__device__ __align__(16) float g_ex2[(size_t)E2T];
__device__ float    g_asrc1[NN * HEADS], g_adst1[NN * HEADS], g_den1[NN * HEADS];
__device__ float    g_asrc2[NN], g_adst2[NN], g_den2[NN];
__device__ float    g_wae1[ED_F * HEADS];      // [d][h]
__device__ float    g_wae2[ED_F];
__device__ float    g_emean[ED_F];
__device__ float    g_sl1[HEADS];
__device__ float    g_sl2[1];
__device__ int      g_is64;

// load edge endpoints for edge e (< EE), honoring runtime dtype flag
__device__ __forceinline__ void load_edge(const void* eidx, int e, int is64, int& se, int& de) {
    if (is64) {
        const long long* p = (const long long*)eidx;
        se = (int)p[e];
        de = (int)p[(size_t)EE + e];
    } else {
        const int* p = (const int*)eidx;
        se = p[e];
        de = p[EE + e];
    }
}

// ---------------- dtype probe: int64 iff all high words of first 256 pairs are zero ----------------
__global__ void probe_dtype(const void* eidx) {
    const int* p = (const int*)eidx;
    int lane = threadIdx.x;
    int allzero = 1;
    #pragma unroll
    for (int i = 0; i < 8; i++) {
        if (p[2 * (lane * 8 + i) + 1] != 0) allzero = 0;
    }
    unsigned vote = __ballot_sync(0xffffffffu, allzero);
    if (lane == 0) g_is64 = (vote == 0xffffffffu) ? 1 : 0;
}

// ---------------- init ----------------
__global__ void init_zero(float* out) {
    int idx = blockIdx.x * blockDim.x + threadIdx.x;
    int total = NN * F1;
    for (int i = idx; i < total; i += gridDim.x * blockDim.x) {
        g_acc1[i] = 0.f;
        if (i < NN * HEADS) g_den1[i] = 0.f;
        if (i < NN)         g_den2[i] = 0.f;
        if (i < ED_F)       g_emean[i] = 0.f;
        if (i < NN * OUTF)  out[i] = 0.f;
    }
}

// ---------------- tiny precomputes ----------------
__global__ void prep_wae(const float* __restrict__ We1, const float* __restrict__ ae1,
                         const float* __restrict__ We2, const float* __restrict__ ae2) {
    int t = threadIdx.x;
    if (t < ED_F * HEADS) {
        int d = t >> 2, h = t & 3;
        float s = 0.f;
        #pragma unroll
        for (int c = 0; c < HID; c++) s += We1[d * F1 + h * HID + c] * ae1[h * HID + c];
        g_wae1[t] = s;
    } else if (t < ED_F * HEADS + ED_F) {
        int d = t - ED_F * HEADS;
        float s = 0.f;
        #pragma unroll
        for (int c = 0; c < OUTF; c++) s += We2[d * OUTF + c] * ae2[c];
        g_wae2[d] = s;
    }
}

__global__ void emean_reduce(const float* __restrict__ ea) {
    __shared__ float s[ED_F];
    if (threadIdx.x < ED_F) s[threadIdx.x] = 0.f;
    __syncthreads();
    int j = threadIdx.x & (ED_F - 1);
    int grp = (blockIdx.x * blockDim.x + threadIdx.x) >> 4;
    int stride = (gridDim.x * blockDim.x) >> 4;
    float acc = 0.f;
    for (int e = grp; e < EE; e += stride) acc += ea[(size_t)e * ED_F + j];
    atomicAdd(&s[j], acc);
    __syncthreads();
    if (threadIdx.x < ED_F) atomicAdd(&g_emean[threadIdx.x], s[threadIdx.x]);
}

__global__ void sl_consts() {
    int t = threadIdx.x;
    const float inv_e = 1.f / (float)EE;
    if (t < HEADS) {
        float s = 0.f;
        #pragma unroll
        for (int d = 0; d < ED_F; d++) s += g_emean[d] * inv_e * g_wae1[d * HEADS + t];
        g_sl1[t] = s;
    } else if (t == HEADS) {
        float s = 0.f;
        #pragma unroll
        for (int d = 0; d < ED_F; d++) s += g_emean[d] * inv_e * g_wae2[d];
        g_sl2[0] = s;
    }
}

// ---------------- GEMM body: C[M,NC] = A[M,K] * B[K,NC], tile 64x32, K%32==0 ----------------
__device__ __forceinline__ void gemm_body(const float* __restrict__ A, const float* __restrict__ B,
                                          float* __restrict__ C, int M, int K, int NC) {
    __shared__ float As[64][33];
    __shared__ float Bs[32][33];
    int row0 = blockIdx.x * 64;
    int col0 = blockIdx.y * 32;
    int tx = threadIdx.x & 31;
    int ty = threadIdx.x >> 5;
    float acc[8];
    #pragma unroll
    for (int r = 0; r < 8; r++) acc[r] = 0.f;
    for (int k0 = 0; k0 < K; k0 += 32) {
        #pragma unroll
        for (int i = 0; i < 8; i++) {
            int idx = threadIdx.x + i * 256;
            int r = idx >> 5, c = idx & 31;
            int gr = row0 + r;
            As[r][c] = (gr < M) ? A[(size_t)gr * K + k0 + c] : 0.f;
        }
        #pragma unroll
        for (int i = 0; i < 4; i++) {
            int idx = threadIdx.x + i * 256;
            int r = idx >> 5, c = idx & 31;
            Bs[r][c] = B[(size_t)(k0 + r) * NC + col0 + c];
        }
        __syncthreads();
        #pragma unroll
        for (int kk = 0; kk < 32; kk++) {
            float bv = Bs[kk][tx];
            #pragma unroll
            for (int r = 0; r < 8; r++) acc[r] += As[ty * 8 + r][kk] * bv;
        }
        __syncthreads();
    }
    #pragma unroll
    for (int r = 0; r < 8; r++) {
        int gr = row0 + ty * 8 + r;
        if (gr < M) C[(size_t)gr * NC + col0 + tx] = acc[r];
    }
}

// Wrappers: device code references the device globals directly (host code must NOT
// pass __device__ symbols as kernel arguments — host shadow address, not device!).
__global__ void gemm1(const float* __restrict__ x, const float* __restrict__ W1) {
    gemm_body(x, W1, g_h1, NN, IN_F, F1);
}
__global__ void gemm2(const float* __restrict__ W2) {
    gemm_body(g_h1, W2, g_h2, NN, F1, OUTF);
}

// ---------------- per-(node,head) attention coefficients, layer 1 ----------------
__global__ void coef1(const float* __restrict__ as1, const float* __restrict__ ad1) {
    int t = blockIdx.x * blockDim.x + threadIdx.x;   // t = n*4 + h
    if (t >= NN * HEADS) return;
    int n = t >> 2, h = t & 3;
    const float* hp = &g_h1[(size_t)n * F1 + h * HID];
    float s = 0.f, d = 0.f;
    #pragma unroll
    for (int c = 0; c < HID; c++) {
        float v = hp[c];
        s += v * as1[h * HID + c];
        d += v * ad1[h * HID + c];
    }
    g_asrc1[t] = s;
    g_adst1[t] = d;
}

// ---------------- layer 1: logits -> exp (max shift cancels) + den ----------------
__global__ void edge1(const void* __restrict__ eidx, const float* __restrict__ ea) {
    int e = blockIdx.x * blockDim.x + threadIdx.x;
    if (e >= E2T) return;
    int se, de;
    float aed[HEADS];
    if (e < EE) {
        load_edge(eidx, e, g_is64, se, de);
        float s0 = 0.f, s1 = 0.f, s2 = 0.f, s3 = 0.f;
        const float* eav = ea + (size_t)e * ED_F;
        #pragma unroll
        for (int d = 0; d < ED_F; d++) {
            float v = eav[d];
            s0 += v * g_wae1[d * HEADS + 0];
            s1 += v * g_wae1[d * HEADS + 1];
            s2 += v * g_wae1[d * HEADS + 2];
            s3 += v * g_wae1[d * HEADS + 3];
        }
        aed[0] = s0; aed[1] = s1; aed[2] = s2; aed[3] = s3;
    } else {
        se = de = e - EE;
        #pragma unroll
        for (int h = 0; h < HEADS; h++) aed[h] = g_sl1[h];
    }
    float4 exv;
    #pragma unroll
    for (int h = 0; h < HEADS; h++) {
        float lg = g_asrc1[se * HEADS + h] + g_adst1[de * HEADS + h] + aed[h];
        lg = (lg > 0.f) ? lg : NEG_SLOPE * lg;
        float ex = __expf(lg);
        (&exv.x)[h] = ex;
        atomicAdd(&g_den1[de * HEADS + h], ex);
    }
    *reinterpret_cast<float4*>(&g_ex1[(size_t)e * HEADS]) = exv;
}

// ---------------- layer 1: feature scatter (warp/edge, scalar atomics) ----------------
__global__ void scatter1(const void* __restrict__ eidx) {
    int w = (blockIdx.x * blockDim.x + threadIdx.x) >> 5;
    if (w >= E2T) return;
    int lane = threadIdx.x & 31;
    int se, de;
    if (w < EE) load_edge(eidx, w, g_is64, se, de);
    else        se = de = w - EE;
    float exl = (lane < HEADS) ? g_ex1[(size_t)w * HEADS + lane] : 0.f;
    float ex = __shfl_sync(0xffffffffu, exl, lane >> 3);  // head of feature chunk = lane/8
    float4 hv = *reinterpret_cast<const float4*>(&g_h1[(size_t)se * F1 + lane * 4]);
    float* dst = &g_acc1[(size_t)de * F1 + lane * 4];
    atomicAdd(dst + 0, ex * hv.x);
    atomicAdd(dst + 1, ex * hv.y);
    atomicAdd(dst + 2, ex * hv.z);
    atomicAdd(dst + 3, ex * hv.w);
}

// ---------------- layer 1 normalize + bias + relu -> g_h1 ----------------
__global__ void normalize1(const float* __restrict__ b1) {
    int idx = blockIdx.x * blockDim.x + threadIdx.x;
    if (idx >= NN * F1) return;
    int n = idx >> 7, f = idx & 127, h = f >> 5;
    float v = g_acc1[idx] / (g_den1[n * HEADS + h] + 1e-16f) + b1[f];
    g_h1[idx] = fmaxf(v, 0.f);
}

// ---------------- layer 2 ----------------
__global__ void coef2(const float* __restrict__ as2, const float* __restrict__ ad2) {
    int n = blockIdx.x * blockDim.x + threadIdx.x;
    if (n >= NN) return;
    const float* hp = &g_h2[(size_t)n * OUTF];
    float s = 0.f, d = 0.f;
    #pragma unroll
    for (int c = 0; c < OUTF; c++) {
        float v = hp[c];
        s += v * as2[c];
        d += v * ad2[c];
    }
    g_asrc2[n] = s;
    g_adst2[n] = d;
}

__global__ void edge2(const void* __restrict__ eidx, const float* __restrict__ ea) {
    int e = blockIdx.x * blockDim.x + threadIdx.x;
    if (e >= E2T) return;
    int se, de;
    float aed;
    if (e < EE) {
        load_edge(eidx, e, g_is64, se, de);
        float s = 0.f;
        const float* eav = ea + (size_t)e * ED_F;
        #pragma unroll
        for (int d = 0; d < ED_F; d++) s += eav[d] * g_wae2[d];
        aed = s;
    } else {
        se = de = e - EE;
        aed = g_sl2[0];
    }
    float lg = g_asrc2[se] + g_adst2[de] + aed;
    lg = (lg > 0.f) ? lg : NEG_SLOPE * lg;
    float ex = __expf(lg);
    g_ex2[e] = ex;
    atomicAdd(&g_den2[de], ex);
}

__global__ void scatter2(const void* __restrict__ eidx, float* __restrict__ out) {
    int idx = blockIdx.x * blockDim.x + threadIdx.x;
    int e = idx >> 3, t = idx & 7;
    if (e >= E2T) return;
    int se, de;
    if (e < EE) load_edge(eidx, e, g_is64, se, de);
    else        se = de = e - EE;
    float ex = g_ex2[e];
    float4 hv = *reinterpret_cast<const float4*>(&g_h2[(size_t)se * OUTF + t * 4]);
    float* dst = &out[(size_t)de * OUTF + t * 4];
    atomicAdd(dst + 0, ex * hv.x);
    atomicAdd(dst + 1, ex * hv.y);
    atomicAdd(dst + 2, ex * hv.z);
    atomicAdd(dst + 3, ex * hv.w);
}

__global__ void normalize2(float* __restrict__ out, const float* __restrict__ b2) {
    int idx = blockIdx.x * blockDim.x + threadIdx.x;
    if (idx >= NN * OUTF) return;
    int n = idx >> 5, c = idx & 31;
    out[idx] = out[idx] / (g_den2[n] + 1e-16f) + b2[c];
}

// ---------------- silent-when-healthy diagnostics ----------------
__global__ void check_h1(const float* x, const float* W1) {
    // single block; prints only if h1 sample is identically zero (deterministic)
    __shared__ float ssum;
    if (threadIdx.x == 0) ssum = 0.f;
    __syncthreads();
    float a = 0.f;
    for (int i = threadIdx.x; i < 4096; i += blockDim.x) a += fabsf(g_h1[i]);
    atomicAdd(&ssum, a);
    __syncthreads();
    if (threadIdx.x == 0 && ssum == 0.f)
        printf("[diag] h1==0: is64=%d x0=%g W1_0=%g den1_0=%g acc1_0=%g\n",
               g_is64, x[0], W1[0], g_den1[0], g_acc1[0]);
}

// ---------------- launch ----------------
extern "C" void kernel_launch(void* const* d_in, const int* in_sizes, int n_in,
                              void* d_out, int out_size) {
    // Size-based mapping (robust to permutations among unique-size tensors).
    int used[64];
    for (int i = 0; i < n_in && i < 64; i++) used[i] = 0;
    auto take = [&](int want) -> const void* {
        for (int i = 0; i < n_in && i < 64; i++)
            if (!used[i] && in_sizes[i] == want) { used[i] = 1; return d_in[i]; }
        return nullptr;
    };
    const float* x   = (const float*)take(NN * IN_F);
    const void*  eix = take(2 * EE);
    const float* ea  = (const float*)take(EE * ED_F);
    const float* W1  = (const float*)take(IN_F * F1);
    const float* We1 = (const float*)take(ED_F * F1);
    const float* W2  = (const float*)take(F1 * OUTF);
    const float* We2 = (const float*)take(ED_F * OUTF);
    const float* g128[4] = {nullptr, nullptr, nullptr, nullptr};
    const float* g32[4]  = {nullptr, nullptr, nullptr, nullptr};
    int n128 = 0, n32 = 0;
    for (int i = 0; i < n_in && i < 64; i++) {
        if (used[i]) continue;
        if (in_sizes[i] == 128 && n128 < 4) g128[n128++] = (const float*)d_in[i];
        else if (in_sizes[i] == 32 && n32 < 4) g32[n32++] = (const float*)d_in[i];
    }
    const float* as1 = g128[0], *ad1 = g128[1], *ae1 = g128[2], *b1 = g128[3];
    const float* as2 = g32[0],  *ad2 = g32[1],  *ae2 = g32[2],  *b2 = g32[3];
    if (!x || !eix || !ea || !W1 || !We1 || !W2 || !We2 || n128 < 4 || n32 < 4) {
        x   = (const float*)d_in[0];  eix = d_in[1];               ea  = (const float*)d_in[2];
        W1  = (const float*)d_in[3];  We1 = (const float*)d_in[4];
        as1 = (const float*)d_in[5];  ad1 = (const float*)d_in[6]; ae1 = (const float*)d_in[7];
        b1  = (const float*)d_in[8];  W2  = (const float*)d_in[9]; We2 = (const float*)d_in[10];
        as2 = (const float*)d_in[11]; ad2 = (const float*)d_in[12]; ae2 = (const float*)d_in[13];
        b2  = (const float*)d_in[14];
    }
    float* out = (float*)d_out;

    const int TB = 256;

    probe_dtype<<<1, 32>>>(eix);
    init_zero<<<(NN * F1 + TB - 1) / TB, TB>>>(out);
    prep_wae<<<1, 128>>>(We1, ae1, We2, ae2);
    emean_reduce<<<256, TB>>>(ea);
    sl_consts<<<1, 32>>>();

    // layer 1
    gemm1<<<dim3((NN + 63) / 64, F1 / 32), TB>>>(x, W1);
    coef1<<<(NN * HEADS + TB - 1) / TB, TB>>>(as1, ad1);
    edge1<<<(E2T + TB - 1) / TB, TB>>>(eix, ea);
    scatter1<<<(int)(((size_t)E2T * 32 + TB - 1) / TB), TB>>>(eix);
    normalize1<<<(NN * F1 + TB - 1) / TB, TB>>>(b1);
    check_h1<<<1, 256>>>(x, W1);

    // layer 2
    gemm2<<<dim3((NN + 63) / 64, 1), TB>>>(W2);
    coef2<<<(NN + TB - 1) / TB, TB>>>(as2, ad2);
    edge2<<<(E2T + TB - 1) / TB, TB>>>(eix, ea);
    scatter2<<<(int)(((size_t)E2T * 8 + TB - 1) / TB), TB>>>(eix, out);
    normalize2<<<(NN * OUTF + TB - 1) / TB, TB>>>(out, b2);
}

// round 7
// speedup vs baseline: 1.6003x; 1.6003x over previous
#include <cuda_runtime.h>
#include <cuda_bf16.h>
#include <cstdint>
#include <cstdio>

#define NN 50000
#define EE 800000
#define E2T (EE + NN)   // 850000 edges incl self-loops
#define IN_F 128
#define ED_F 16
#define F1 128          // HEADS*HID
#define HEADS 4
#define HID 32
#define OUTF 32
#define NEG_SLOPE 0.2f

// ---------------- scratch (device globals; no allocation allowed) ----------------
__device__ __align__(16) float g_h1[(size_t)NN * F1];     // layer1 features, then relu output
__device__ __align__(16) float g_acc1[(size_t)NN * F1];   // layer1 aggregation accumulator
__device__ __align__(16) float g_h2[(size_t)NN * OUTF];   // layer2 transformed features
__device__ __align__(16) float g_aed1[(size_t)EE * HEADS];// per-edge attention dots, layer1
__device__ __align__(16) float g_aed2[(size_t)EE];        // per-edge attention dots, layer2
__device__ float    g_asrc1[NN * HEADS], g_adst1[NN * HEADS], g_den1[NN * HEADS];
__device__ float    g_asrc2[NN], g_adst2[NN], g_den2[NN];
__device__ float    g_wae1[ED_F * HEADS];      // [d][h]
__device__ float    g_wae2[ED_F];
__device__ float    g_emean[ED_F];
__device__ float    g_sl1[HEADS];
__device__ float    g_sl2[1];
__device__ int      g_is64;

// load edge endpoints for edge e (< EE), honoring runtime dtype flag
__device__ __forceinline__ void load_edge(const void* eidx, int e, int is64, int& se, int& de) {
    if (is64) {
        const long long* p = (const long long*)eidx;
        se = (int)p[e];
        de = (int)p[(size_t)EE + e];
    } else {
        const int* p = (const int*)eidx;
        se = p[e];
        de = p[EE + e];
    }
}

// ---------------- dtype probe ----------------
__global__ void probe_dtype(const void* eidx) {
    const int* p = (const int*)eidx;
    int lane = threadIdx.x;
    int allzero = 1;
    #pragma unroll
    for (int i = 0; i < 8; i++) {
        if (p[2 * (lane * 8 + i) + 1] != 0) allzero = 0;
    }
    unsigned vote = __ballot_sync(0xffffffffu, allzero);
    if (lane == 0) g_is64 = (vote == 0xffffffffu) ? 1 : 0;
}

// ---------------- init ----------------
__global__ void init_zero(float* out) {
    int idx = blockIdx.x * blockDim.x + threadIdx.x;
    int total = NN * F1;
    for (int i = idx; i < total; i += gridDim.x * blockDim.x) {
        g_acc1[i] = 0.f;
        if (i < NN * HEADS) g_den1[i] = 0.f;
        if (i < NN)         g_den2[i] = 0.f;
        if (i < ED_F)       g_emean[i] = 0.f;
        if (i < NN * OUTF)  out[i] = 0.f;
    }
}

// ---------------- tiny precomputes ----------------
__global__ void prep_wae(const float* __restrict__ We1, const float* __restrict__ ae1,
                         const float* __restrict__ We2, const float* __restrict__ ae2) {
    int t = threadIdx.x;
    if (t < ED_F * HEADS) {
        int d = t >> 2, h = t & 3;
        float s = 0.f;
        #pragma unroll
        for (int c = 0; c < HID; c++) s += We1[d * F1 + h * HID + c] * ae1[h * HID + c];
        g_wae1[t] = s;
    } else if (t < ED_F * HEADS + ED_F) {
        int d = t - ED_F * HEADS;
        float s = 0.f;
        #pragma unroll
        for (int c = 0; c < OUTF; c++) s += We2[d * OUTF + c] * ae2[c];
        g_wae2[d] = s;
    }
}

// ---------------- ONE pass over edge_attr: aed1 (4), aed2 (1), emean sums ----------------
__global__ void edge_dots(const float* __restrict__ ea) {
    __shared__ float s16[ED_F];
    if (threadIdx.x < ED_F) s16[threadIdx.x] = 0.f;
    __syncthreads();
    int e = blockIdx.x * blockDim.x + threadIdx.x;
    float4 q[4];
    if (e < EE) {
        const float4* eav = reinterpret_cast<const float4*>(ea + (size_t)e * ED_F);
        #pragma unroll
        for (int i = 0; i < 4; i++) q[i] = eav[i];
        // attention dots
        float a0 = 0.f, a1 = 0.f, a2 = 0.f, a3 = 0.f, a4 = 0.f;
        #pragma unroll
        for (int i = 0; i < 4; i++) {
            const float* v = &q[i].x;
            #pragma unroll
            for (int j = 0; j < 4; j++) {
                int d = i * 4 + j;
                float vv = v[j];
                a0 += vv * g_wae1[d * HEADS + 0];
                a1 += vv * g_wae1[d * HEADS + 1];
                a2 += vv * g_wae1[d * HEADS + 2];
                a3 += vv * g_wae1[d * HEADS + 3];
                a4 += vv * g_wae2[d];
            }
        }
        *reinterpret_cast<float4*>(&g_aed1[(size_t)e * HEADS]) = make_float4(a0, a1, a2, a3);
        g_aed2[e] = a4;
    } else {
        #pragma unroll
        for (int i = 0; i < 4; i++) q[i] = make_float4(0.f, 0.f, 0.f, 0.f);
    }
    // warp reduce the 16 emean partials
    #pragma unroll
    for (int o = 16; o; o >>= 1) {
        #pragma unroll
        for (int i = 0; i < 4; i++) {
            q[i].x += __shfl_xor_sync(0xffffffffu, q[i].x, o);
            q[i].y += __shfl_xor_sync(0xffffffffu, q[i].y, o);
            q[i].z += __shfl_xor_sync(0xffffffffu, q[i].z, o);
            q[i].w += __shfl_xor_sync(0xffffffffu, q[i].w, o);
        }
    }
    if ((threadIdx.x & 31) == 0) {
        #pragma unroll
        for (int i = 0; i < 4; i++) {
            atomicAdd(&s16[i * 4 + 0], q[i].x);
            atomicAdd(&s16[i * 4 + 1], q[i].y);
            atomicAdd(&s16[i * 4 + 2], q[i].z);
            atomicAdd(&s16[i * 4 + 3], q[i].w);
        }
    }
    __syncthreads();
    if (threadIdx.x < ED_F) atomicAdd(&g_emean[threadIdx.x], s16[threadIdx.x]);
}

__global__ void sl_consts() {
    int t = threadIdx.x;
    const float inv_e = 1.f / (float)EE;
    if (t < HEADS) {
        float s = 0.f;
        #pragma unroll
        for (int d = 0; d < ED_F; d++) s += g_emean[d] * inv_e * g_wae1[d * HEADS + t];
        g_sl1[t] = s;
    } else if (t == HEADS) {
        float s = 0.f;
        #pragma unroll
        for (int d = 0; d < ED_F; d++) s += g_emean[d] * inv_e * g_wae2[d];
        g_sl2[0] = s;
    }
}

// ---------------- GEMM body: C[M,NC] = A[M,K] * B[K,NC], tile 64x32 ----------------
__device__ __forceinline__ void gemm_body(const float* __restrict__ A, const float* __restrict__ B,
                                          float* __restrict__ C, int M, int K, int NC) {
    __shared__ float As[64][33];
    __shared__ float Bs[32][33];
    int row0 = blockIdx.x * 64;
    int col0 = blockIdx.y * 32;
    int tx = threadIdx.x & 31;
    int ty = threadIdx.x >> 5;
    float acc[8];
    #pragma unroll
    for (int r = 0; r < 8; r++) acc[r] = 0.f;
    for (int k0 = 0; k0 < K; k0 += 32) {
        #pragma unroll
        for (int i = 0; i < 8; i++) {
            int idx = threadIdx.x + i * 256;
            int r = idx >> 5, c = idx & 31;
            int gr = row0 + r;
            As[r][c] = (gr < M) ? A[(size_t)gr * K + k0 + c] : 0.f;
        }
        #pragma unroll
        for (int i = 0; i < 4; i++) {
            int idx = threadIdx.x + i * 256;
            int r = idx >> 5, c = idx & 31;
            Bs[r][c] = B[(size_t)(k0 + r) * NC + col0 + c];
        }
        __syncthreads();
        #pragma unroll
        for (int kk = 0; kk < 32; kk++) {
            float bv = Bs[kk][tx];
            #pragma unroll
            for (int r = 0; r < 8; r++) acc[r] += As[ty * 8 + r][kk] * bv;
        }
        __syncthreads();
    }
    #pragma unroll
    for (int r = 0; r < 8; r++) {
        int gr = row0 + ty * 8 + r;
        if (gr < M) C[(size_t)gr * NC + col0 + tx] = acc[r];
    }
}
__global__ void gemm1(const float* __restrict__ x, const float* __restrict__ W1) {
    gemm_body(x, W1, g_h1, NN, IN_F, F1);
}
__global__ void gemm2(const float* __restrict__ W2) {
    gemm_body(g_h1, W2, g_h2, NN, F1, OUTF);
}

// ---------------- per-(node,head) attention coefficients ----------------
__global__ void coef1(const float* __restrict__ as1, const float* __restrict__ ad1) {
    int t = blockIdx.x * blockDim.x + threadIdx.x;   // t = n*4 + h
    if (t >= NN * HEADS) return;
    int n = t >> 2, h = t & 3;
    const float* hp = &g_h1[(size_t)n * F1 + h * HID];
    float s = 0.f, d = 0.f;
    #pragma unroll
    for (int c = 0; c < HID; c++) {
        float v = hp[c];
        s += v * as1[h * HID + c];
        d += v * ad1[h * HID + c];
    }
    g_asrc1[t] = s;
    g_adst1[t] = d;
}

// ---------------- layer 1 fused: logits+exp+den+feature scatter (warp/edge) ----------------
__global__ void scatter1(const void* __restrict__ eidx) {
    int w = (blockIdx.x * blockDim.x + threadIdx.x) >> 5;
    if (w >= E2T) return;
    int lane = threadIdx.x & 31;
    int se, de;
    float aed = 0.f;
    if (w < EE) {
        load_edge(eidx, w, g_is64, se, de);
        if (lane < HEADS) aed = g_aed1[(size_t)w * HEADS + lane];
    } else {
        se = de = w - EE;
        if (lane < HEADS) aed = g_sl1[lane];
    }
    float ex = 0.f;
    if (lane < HEADS) {
        float lg = g_asrc1[se * HEADS + lane] + g_adst1[de * HEADS + lane] + aed;
        lg = (lg > 0.f) ? lg : NEG_SLOPE * lg;
        ex = __expf(lg);
        atomicAdd(&g_den1[de * HEADS + lane], ex);
    }
    float exb = __shfl_sync(0xffffffffu, ex, lane >> 3);  // head of feature chunk = lane/8
    float4 hv = *reinterpret_cast<const float4*>(&g_h1[(size_t)se * F1 + lane * 4]);
    float4 v = make_float4(exb * hv.x, exb * hv.y, exb * hv.z, exb * hv.w);
    atomicAdd(reinterpret_cast<float4*>(&g_acc1[(size_t)de * F1 + lane * 4]), v);
}

// ---------------- layer 1 normalize + bias + relu -> g_h1 ----------------
__global__ void normalize1(const float* __restrict__ b1) {
    int idx = blockIdx.x * blockDim.x + threadIdx.x;
    if (idx >= NN * F1) return;
    int n = idx >> 7, f = idx & 127, h = f >> 5;
    float v = g_acc1[idx] / (g_den1[n * HEADS + h] + 1e-16f) + b1[f];
    g_h1[idx] = fmaxf(v, 0.f);
}

// ---------------- layer 2 ----------------
__global__ void coef2(const float* __restrict__ as2, const float* __restrict__ ad2) {
    int n = blockIdx.x * blockDim.x + threadIdx.x;
    if (n >= NN) return;
    const float* hp = &g_h2[(size_t)n * OUTF];
    float s = 0.f, d = 0.f;
    #pragma unroll
    for (int c = 0; c < OUTF; c++) {
        float v = hp[c];
        s += v * as2[c];
        d += v * ad2[c];
    }
    g_asrc2[n] = s;
    g_adst2[n] = d;
}

// layer 2 fused: logits+exp+den+scatter (8 threads/edge)
__global__ void scatter2(const void* __restrict__ eidx, float* __restrict__ out) {
    int idx = blockIdx.x * blockDim.x + threadIdx.x;
    int e = idx >> 3, t = idx & 7;
    if (e >= E2T) return;
    int lane = threadIdx.x & 31;
    int se, de;
    if (e < EE) load_edge(eidx, e, g_is64, se, de);
    else        se = de = e - EE;
    float ex = 0.f;
    if (t == 0) {
        float aed = (e < EE) ? g_aed2[e] : g_sl2[0];
        float lg = g_asrc2[se] + g_adst2[de] + aed;
        lg = (lg > 0.f) ? lg : NEG_SLOPE * lg;
        ex = __expf(lg);
        atomicAdd(&g_den2[de], ex);
    }
    ex = __shfl_sync(0xffffffffu, ex, lane & ~7);
    float4 hv = *reinterpret_cast<const float4*>(&g_h2[(size_t)se * OUTF + t * 4]);
    float4 v = make_float4(ex * hv.x, ex * hv.y, ex * hv.z, ex * hv.w);
    atomicAdd(reinterpret_cast<float4*>(&out[(size_t)de * OUTF + t * 4]), v);
}

__global__ void normalize2(float* __restrict__ out, const float* __restrict__ b2) {
    int idx = blockIdx.x * blockDim.x + threadIdx.x;
    if (idx >= NN * OUTF) return;
    int n = idx >> 5, c = idx & 31;
    out[idx] = out[idx] / (g_den2[n] + 1e-16f) + b2[c];
}

// ---------------- silent-when-healthy diagnostics ----------------
__global__ void check_h1(const float* x, const float* W1) {
    __shared__ float ssum;
    if (threadIdx.x == 0) ssum = 0.f;
    __syncthreads();
    float a = 0.f;
    for (int i = threadIdx.x; i < 4096; i += blockDim.x) a += fabsf(g_h1[i]);
    atomicAdd(&ssum, a);
    __syncthreads();
    if (threadIdx.x == 0 && ssum == 0.f)
        printf("[diag] h1==0: is64=%d x0=%g W1_0=%g den1_0=%g acc1_0=%g\n",
               g_is64, x[0], W1[0], g_den1[0], g_acc1[0]);
}

// ---------------- launch ----------------
extern "C" void kernel_launch(void* const* d_in, const int* in_sizes, int n_in,
                              void* d_out, int out_size) {
    int used[64];
    for (int i = 0; i < n_in && i < 64; i++) used[i] = 0;
    auto take = [&](int want) -> const void* {
        for (int i = 0; i < n_in && i < 64; i++)
            if (!used[i] && in_sizes[i] == want) { used[i] = 1; return d_in[i]; }
        return nullptr;
    };
    const float* x   = (const float*)take(NN * IN_F);
    const void*  eix = take(2 * EE);
    const float* ea  = (const float*)take(EE * ED_F);
    const float* W1  = (const float*)take(IN_F * F1);
    const float* We1 = (const float*)take(ED_F * F1);
    const float* W2  = (const float*)take(F1 * OUTF);
    const float* We2 = (const float*)take(ED_F * OUTF);
    const float* g128[4] = {nullptr, nullptr, nullptr, nullptr};
    const float* g32[4]  = {nullptr, nullptr, nullptr, nullptr};
    int n128 = 0, n32 = 0;
    for (int i = 0; i < n_in && i < 64; i++) {
        if (used[i]) continue;
        if (in_sizes[i] == 128 && n128 < 4) g128[n128++] = (const float*)d_in[i];
        else if (in_sizes[i] == 32 && n32 < 4) g32[n32++] = (const float*)d_in[i];
    }
    const float* as1 = g128[0], *ad1 = g128[1], *ae1 = g128[2], *b1 = g128[3];
    const float* as2 = g32[0],  *ad2 = g32[1],  *ae2 = g32[2],  *b2 = g32[3];
    if (!x || !eix || !ea || !W1 || !We1 || !W2 || !We2 || n128 < 4 || n32 < 4) {
        x   = (const float*)d_in[0];  eix = d_in[1];               ea  = (const float*)d_in[2];
        W1  = (const float*)d_in[3];  We1 = (const float*)d_in[4];
        as1 = (const float*)d_in[5];  ad1 = (const float*)d_in[6]; ae1 = (const float*)d_in[7];
        b1  = (const float*)d_in[8];  W2  = (const float*)d_in[9]; We2 = (const float*)d_in[10];
        as2 = (const float*)d_in[11]; ad2 = (const float*)d_in[12]; ae2 = (const float*)d_in[13];
        b2  = (const float*)d_in[14];
    }
    float* out = (float*)d_out;

    const int TB = 256;

    probe_dtype<<<1, 32>>>(eix);
    init_zero<<<(NN * F1 + TB - 1) / TB, TB>>>(out);
    prep_wae<<<1, 128>>>(We1, ae1, We2, ae2);
    edge_dots<<<(EE + TB - 1) / TB, TB>>>(ea);
    sl_consts<<<1, 32>>>();

    // layer 1
    gemm1<<<dim3((NN + 63) / 64, F1 / 32), TB>>>(x, W1);
    coef1<<<(NN * HEADS + TB - 1) / TB, TB>>>(as1, ad1);
    scatter1<<<(int)(((size_t)E2T * 32 + TB - 1) / TB), TB>>>(eix);
    normalize1<<<(NN * F1 + TB - 1) / TB, TB>>>(b1);
    check_h1<<<1, 256>>>(x, W1);

    // layer 2
    gemm2<<<dim3((NN + 63) / 64, 1), TB>>>(W2);
    coef2<<<(NN + TB - 1) / TB, TB>>>(as2, ad2);
    scatter2<<<(int)(((size_t)E2T * 8 + TB - 1) / TB), TB>>>(eix, out);
    normalize2<<<(NN * OUTF + TB - 1) / TB, TB>>>(out, b2);
}

// round 8
// speedup vs baseline: 1.6912x; 1.0568x over previous
#include <cuda_runtime.h>
#include <cuda_bf16.h>
#include <cstdint>

#define NN 50000
#define EE 800000
#define E2T (EE + NN)   // 850000 edges incl self-loops
#define IN_F 128
#define ED_F 16
#define F1 128          // HEADS*HID
#define HEADS 4
#define HID 32
#define OUTF 32
#define NEG_SLOPE 0.2f

// ---------------- scratch (device globals) ----------------
__device__ __align__(16) float g_h1[(size_t)NN * F1];     // layer1 transformed features
__device__ __align__(16) float g_hr[(size_t)NN * F1];     // layer1 aggregated+relu output
__device__ __align__(16) float g_h2[(size_t)NN * OUTF];   // layer2 transformed features
__device__ __align__(16) float4 g_saed1[(size_t)E2T];     // sorted per-edge dots, layer1 (4 heads)
__device__ float    g_saed2[(size_t)E2T];                 // sorted per-edge dots, layer2
__device__ int      g_ssrc[(size_t)E2T];                  // sorted src ids
__device__ int      g_count[NN];
__device__ int      g_rowstart[NN + 1];
__device__ int      g_cursor[NN];
__device__ float    g_asrc1[NN * HEADS], g_adst1[NN * HEADS];
__device__ float    g_asrc2[NN], g_adst2[NN];
__device__ float    g_wae1[ED_F * HEADS];      // [d][h]
__device__ float    g_wae2[ED_F];
__device__ float    g_emean[ED_F];
__device__ float    g_sl1[HEADS];
__device__ float    g_sl2[1];
__device__ int      g_is64;

__device__ __forceinline__ void load_edge(const void* eidx, int e, int is64, int& se, int& de) {
    if (is64) {
        const long long* p = (const long long*)eidx;
        se = (int)p[e];
        de = (int)p[(size_t)EE + e];
    } else {
        const int* p = (const int*)eidx;
        se = p[e];
        de = p[EE + e];
    }
}

// ---------------- dtype probe ----------------
__global__ void probe_dtype(const void* eidx) {
    const int* p = (const int*)eidx;
    int lane = threadIdx.x;
    int allzero = 1;
    #pragma unroll
    for (int i = 0; i < 8; i++)
        if (p[2 * (lane * 8 + i) + 1] != 0) allzero = 0;
    unsigned vote = __ballot_sync(0xffffffffu, allzero);
    if (lane == 0) g_is64 = (vote == 0xffffffffu) ? 1 : 0;
}

// ---------------- init counters ----------------
__global__ void init0() {
    int i = blockIdx.x * blockDim.x + threadIdx.x;
    if (i < NN) g_count[i] = 0;
    if (i < ED_F) g_emean[i] = 0.f;
}

// ---------------- tiny precomputes ----------------
__global__ void prep_wae(const float* __restrict__ We1, const float* __restrict__ ae1,
                         const float* __restrict__ We2, const float* __restrict__ ae2) {
    int t = threadIdx.x;
    if (t < ED_F * HEADS) {
        int d = t >> 2, h = t & 3;
        float s = 0.f;
        #pragma unroll
        for (int c = 0; c < HID; c++) s += We1[d * F1 + h * HID + c] * ae1[h * HID + c];
        g_wae1[t] = s;
    } else if (t < ED_F * HEADS + ED_F) {
        int d = t - ED_F * HEADS;
        float s = 0.f;
        #pragma unroll
        for (int c = 0; c < OUTF; c++) s += We2[d * OUTF + c] * ae2[c];
        g_wae2[d] = s;
    }
}

// ---------------- CSR: count in-degree ----------------
__global__ void count_edges(const void* __restrict__ eidx) {
    int e = blockIdx.x * blockDim.x + threadIdx.x;
    if (e >= EE) return;
    int de;
    if (g_is64) de = (int)((const long long*)eidx)[(size_t)EE + e];
    else        de = ((const int*)eidx)[EE + e];
    atomicAdd(&g_count[de], 1);
}

// ---------------- CSR: single-block scan (deg+1 per node; slot0 = self-loop) ----------------
__global__ void scan_rows() {
    __shared__ int ssum[1024];
    const int CH = (NN + 1023) / 1024;  // 49
    int tid = threadIdx.x;
    int base = tid * CH;
    int local = 0;
    for (int i = 0; i < CH; i++) {
        int idx = base + i;
        if (idx < NN) local += g_count[idx] + 1;
    }
    ssum[tid] = local;
    __syncthreads();
    for (int o = 1; o < 1024; o <<= 1) {
        int v = (tid >= o) ? ssum[tid - o] : 0;
        __syncthreads();
        ssum[tid] += v;
        __syncthreads();
    }
    int run = (tid == 0) ? 0 : ssum[tid - 1];
    for (int i = 0; i < CH; i++) {
        int idx = base + i;
        if (idx < NN) {
            g_rowstart[idx] = run;
            g_cursor[idx] = run + 1;   // reserve slot 0 for self-loop
            run += g_count[idx] + 1;
        }
    }
    if (tid == 1023) g_rowstart[NN] = run;
}

// ---------------- edge dots + scatter into CSR order + emean partials ----------------
__global__ void edge_dots_scatter(const void* __restrict__ eidx, const float* __restrict__ ea) {
    __shared__ float s16[ED_F];
    if (threadIdx.x < ED_F) s16[threadIdx.x] = 0.f;
    __syncthreads();
    int e = blockIdx.x * blockDim.x + threadIdx.x;
    float4 q[4];
    if (e < EE) {
        const float4* eav = reinterpret_cast<const float4*>(ea + (size_t)e * ED_F);
        #pragma unroll
        for (int i = 0; i < 4; i++) q[i] = eav[i];
        float a0 = 0.f, a1 = 0.f, a2 = 0.f, a3 = 0.f, a4 = 0.f;
        #pragma unroll
        for (int i = 0; i < 4; i++) {
            const float* v = &q[i].x;
            #pragma unroll
            for (int j = 0; j < 4; j++) {
                int d = i * 4 + j;
                float vv = v[j];
                a0 += vv * g_wae1[d * HEADS + 0];
                a1 += vv * g_wae1[d * HEADS + 1];
                a2 += vv * g_wae1[d * HEADS + 2];
                a3 += vv * g_wae1[d * HEADS + 3];
                a4 += vv * g_wae2[d];
            }
        }
        int se, de;
        load_edge(eidx, e, g_is64, se, de);
        int pos = atomicAdd(&g_cursor[de], 1);
        g_ssrc[pos] = se;
        g_saed1[pos] = make_float4(a0, a1, a2, a3);
        g_saed2[pos] = a4;
    } else {
        #pragma unroll
        for (int i = 0; i < 4; i++) q[i] = make_float4(0.f, 0.f, 0.f, 0.f);
    }
    #pragma unroll
    for (int o = 16; o; o >>= 1) {
        #pragma unroll
        for (int i = 0; i < 4; i++) {
            q[i].x += __shfl_xor_sync(0xffffffffu, q[i].x, o);
            q[i].y += __shfl_xor_sync(0xffffffffu, q[i].y, o);
            q[i].z += __shfl_xor_sync(0xffffffffu, q[i].z, o);
            q[i].w += __shfl_xor_sync(0xffffffffu, q[i].w, o);
        }
    }
    if ((threadIdx.x & 31) == 0) {
        #pragma unroll
        for (int i = 0; i < 4; i++) {
            atomicAdd(&s16[i * 4 + 0], q[i].x);
            atomicAdd(&s16[i * 4 + 1], q[i].y);
            atomicAdd(&s16[i * 4 + 2], q[i].z);
            atomicAdd(&s16[i * 4 + 3], q[i].w);
        }
    }
    __syncthreads();
    if (threadIdx.x < ED_F) atomicAdd(&g_emean[threadIdx.x], s16[threadIdx.x]);
}

__global__ void sl_consts() {
    int t = threadIdx.x;
    const float inv_e = 1.f / (float)EE;
    if (t < HEADS) {
        float s = 0.f;
        #pragma unroll
        for (int d = 0; d < ED_F; d++) s += g_emean[d] * inv_e * g_wae1[d * HEADS + t];
        g_sl1[t] = s;
    } else if (t == HEADS) {
        float s = 0.f;
        #pragma unroll
        for (int d = 0; d < ED_F; d++) s += g_emean[d] * inv_e * g_wae2[d];
        g_sl2[0] = s;
    }
}

// ---------------- self-loop fill (slot 0 of each segment) ----------------
__global__ void selfloop_fill() {
    int n = blockIdx.x * blockDim.x + threadIdx.x;
    if (n >= NN) return;
    int j = g_rowstart[n];
    g_ssrc[j] = n;
    g_saed1[j] = make_float4(g_sl1[0], g_sl1[1], g_sl1[2], g_sl1[3]);
    g_saed2[j] = g_sl2[0];
}

// ---------------- GEMM1: h1 = x @ W1, fused coef1 epilogue ----------------
__global__ void gemm1(const float* __restrict__ A, const float* __restrict__ B,
                      const float* __restrict__ as1, const float* __restrict__ ad1) {
    __shared__ float As[64][33];
    __shared__ float Bs[32][33];
    const int M = NN, K = IN_F, NC = F1;
    int row0 = blockIdx.x * 64;
    int col0 = blockIdx.y * 32;   // head h = blockIdx.y
    int h = blockIdx.y;
    int tx = threadIdx.x & 31;
    int ty = threadIdx.x >> 5;
    float acc[8];
    #pragma unroll
    for (int r = 0; r < 8; r++) acc[r] = 0.f;
    for (int k0 = 0; k0 < K; k0 += 32) {
        #pragma unroll
        for (int i = 0; i < 8; i++) {
            int idx = threadIdx.x + i * 256;
            int r = idx >> 5, c = idx & 31;
            int gr = row0 + r;
            As[r][c] = (gr < M) ? A[(size_t)gr * K + k0 + c] : 0.f;
        }
        #pragma unroll
        for (int i = 0; i < 4; i++) {
            int idx = threadIdx.x + i * 256;
            int r = idx >> 5, c = idx & 31;
            Bs[r][c] = B[(size_t)(k0 + r) * NC + col0 + c];
        }
        __syncthreads();
        #pragma unroll
        for (int kk = 0; kk < 32; kk++) {
            float bv = Bs[kk][tx];
            #pragma unroll
            for (int r = 0; r < 8; r++) acc[r] += As[ty * 8 + r][kk] * bv;
        }
        __syncthreads();
    }
    float asv = as1[h * HID + tx];
    float adv = ad1[h * HID + tx];
    #pragma unroll
    for (int r = 0; r < 8; r++) {
        int gr = row0 + ty * 8 + r;
        if (gr < M) C_STORE: ;
        if (gr < M) g_h1[(size_t)gr * NC + col0 + tx] = acc[r];
        float sv = acc[r] * asv;
        float dv = acc[r] * adv;
        #pragma unroll
        for (int o = 16; o; o >>= 1) {
            sv += __shfl_xor_sync(0xffffffffu, sv, o);
            dv += __shfl_xor_sync(0xffffffffu, dv, o);
        }
        if (tx == 0 && gr < M) {
            g_asrc1[gr * HEADS + h] = sv;
            g_adst1[gr * HEADS + h] = dv;
        }
    }
}

// ---------------- aggregate layer 1 (warp per node; no atomics) ----------------
__global__ void aggregate1(const float* __restrict__ b1) {
    int n = (blockIdx.x * blockDim.x + threadIdx.x) >> 5;
    if (n >= NN) return;
    int lane = threadIdx.x & 31;
    int beg = g_rowstart[n];
    int end = g_rowstart[n + 1];
    float adst = (lane < HEADS) ? g_adst1[n * HEADS + lane] : 0.f;
    float den = 0.f;
    float4 acc = make_float4(0.f, 0.f, 0.f, 0.f);
    for (int j = beg; j < end; j++) {
        int se = g_ssrc[j];
        float ex = 0.f;
        if (lane < HEADS) {
            float aed = ((const float*)&g_saed1[j])[lane];
            float lg = g_asrc1[se * HEADS + lane] + adst + aed;
            lg = (lg > 0.f) ? lg : NEG_SLOPE * lg;
            ex = __expf(lg);
            den += ex;
        }
        float exb = __shfl_sync(0xffffffffu, ex, lane >> 3);  // head = lane/8
        float4 hv = *reinterpret_cast<const float4*>(&g_h1[(size_t)se * F1 + lane * 4]);
        acc.x += exb * hv.x;
        acc.y += exb * hv.y;
        acc.z += exb * hv.z;
        acc.w += exb * hv.w;
    }
    float denh = __shfl_sync(0xffffffffu, den, lane >> 3);
    float inv = 1.f / (denh + 1e-16f);
    float4 bv = *reinterpret_cast<const float4*>(&b1[lane * 4]);
    float4 o;
    o.x = fmaxf(acc.x * inv + bv.x, 0.f);
    o.y = fmaxf(acc.y * inv + bv.y, 0.f);
    o.z = fmaxf(acc.z * inv + bv.z, 0.f);
    o.w = fmaxf(acc.w * inv + bv.w, 0.f);
    *reinterpret_cast<float4*>(&g_hr[(size_t)n * F1 + lane * 4]) = o;
}

// ---------------- GEMM2: h2 = hr @ W2, fused coef2 epilogue ----------------
__global__ void gemm2(const float* __restrict__ B,
                      const float* __restrict__ as2, const float* __restrict__ ad2) {
    __shared__ float As[64][33];
    __shared__ float Bs[32][33];
    const int M = NN, K = F1, NC = OUTF;
    int row0 = blockIdx.x * 64;
    int tx = threadIdx.x & 31;
    int ty = threadIdx.x >> 5;
    float acc[8];
    #pragma unroll
    for (int r = 0; r < 8; r++) acc[r] = 0.f;
    for (int k0 = 0; k0 < K; k0 += 32) {
        #pragma unroll
        for (int i = 0; i < 8; i++) {
            int idx = threadIdx.x + i * 256;
            int r = idx >> 5, c = idx & 31;
            int gr = row0 + r;
            As[r][c] = (gr < M) ? g_hr[(size_t)gr * K + k0 + c] : 0.f;
        }
        #pragma unroll
        for (int i = 0; i < 4; i++) {
            int idx = threadIdx.x + i * 256;
            int r = idx >> 5, c = idx & 31;
            Bs[r][c] = B[(size_t)(k0 + r) * NC + c];
        }
        __syncthreads();
        #pragma unroll
        for (int kk = 0; kk < 32; kk++) {
            float bv = Bs[kk][tx];
            #pragma unroll
            for (int r = 0; r < 8; r++) acc[r] += As[ty * 8 + r][kk] * bv;
        }
        __syncthreads();
    }
    float asv = as2[tx];
    float adv = ad2[tx];
    #pragma unroll
    for (int r = 0; r < 8; r++) {
        int gr = row0 + ty * 8 + r;
        if (gr < M) g_h2[(size_t)gr * NC + tx] = acc[r];
        float sv = acc[r] * asv;
        float dv = acc[r] * adv;
        #pragma unroll
        for (int o = 16; o; o >>= 1) {
            sv += __shfl_xor_sync(0xffffffffu, sv, o);
            dv += __shfl_xor_sync(0xffffffffu, dv, o);
        }
        if (tx == 0 && gr < M) {
            g_asrc2[gr] = sv;
            g_adst2[gr] = dv;
        }
    }
}

// ---------------- aggregate layer 2 (warp per node; writes final out) ----------------
__global__ void aggregate2(float* __restrict__ out, const float* __restrict__ b2) {
    int n = (blockIdx.x * blockDim.x + threadIdx.x) >> 5;
    if (n >= NN) return;
    int lane = threadIdx.x & 31;
    int beg = g_rowstart[n];
    int end = g_rowstart[n + 1];
    float adst = g_adst2[n];
    float den = 0.f, acc = 0.f;
    for (int j = beg; j < end; j++) {
        int se = g_ssrc[j];
        float lg = g_asrc2[se] + adst + g_saed2[j];   // uniform across warp
        lg = (lg > 0.f) ? lg : NEG_SLOPE * lg;
        float ex = __expf(lg);
        den += ex;
        acc += ex * g_h2[(size_t)se * OUTF + lane];
    }
    out[(size_t)n * OUTF + lane] = acc / (den + 1e-16f) + b2[lane];
}

// ---------------- launch ----------------
extern "C" void kernel_launch(void* const* d_in, const int* in_sizes, int n_in,
                              void* d_out, int out_size) {
    int used[64];
    for (int i = 0; i < n_in && i < 64; i++) used[i] = 0;
    auto take = [&](int want) -> const void* {
        for (int i = 0; i < n_in && i < 64; i++)
            if (!used[i] && in_sizes[i] == want) { used[i] = 1; return d_in[i]; }
        return nullptr;
    };
    const float* x   = (const float*)take(NN * IN_F);
    const void*  eix = take(2 * EE);
    const float* ea  = (const float*)take(EE * ED_F);
    const float* W1  = (const float*)take(IN_F * F1);
    const float* We1 = (const float*)take(ED_F * F1);
    const float* W2  = (const float*)take(F1 * OUTF);
    const float* We2 = (const float*)take(ED_F * OUTF);
    const float* g128[4] = {nullptr, nullptr, nullptr, nullptr};
    const float* g32[4]  = {nullptr, nullptr, nullptr, nullptr};
    int n128 = 0, n32 = 0;
    for (int i = 0; i < n_in && i < 64; i++) {
        if (used[i]) continue;
        if (in_sizes[i] == 128 && n128 < 4) g128[n128++] = (const float*)d_in[i];
        else if (in_sizes[i] == 32 && n32 < 4) g32[n32++] = (const float*)d_in[i];
    }
    const float* as1 = g128[0], *ad1 = g128[1], *ae1 = g128[2], *b1 = g128[3];
    const float* as2 = g32[0],  *ad2 = g32[1],  *ae2 = g32[2],  *b2 = g32[3];
    if (!x || !eix || !ea || !W1 || !We1 || !W2 || !We2 || n128 < 4 || n32 < 4) {
        x   = (const float*)d_in[0];  eix = d_in[1];               ea  = (const float*)d_in[2];
        W1  = (const float*)d_in[3];  We1 = (const float*)d_in[4];
        as1 = (const float*)d_in[5];  ad1 = (const float*)d_in[6]; ae1 = (const float*)d_in[7];
        b1  = (const float*)d_in[8];  W2  = (const float*)d_in[9]; We2 = (const float*)d_in[10];
        as2 = (const float*)d_in[11]; ad2 = (const float*)d_in[12]; ae2 = (const float*)d_in[13];
        b2  = (const float*)d_in[14];
    }
    float* out = (float*)d_out;

    const int TB = 256;

    probe_dtype<<<1, 32>>>(eix);
    init0<<<(NN + TB - 1) / TB, TB>>>();
    prep_wae<<<1, 128>>>(We1, ae1, We2, ae2);
    count_edges<<<(EE + TB - 1) / TB, TB>>>(eix);
    scan_rows<<<1, 1024>>>();
    edge_dots_scatter<<<(EE + TB - 1) / TB, TB>>>(eix, ea);
    sl_consts<<<1, 32>>>();
    selfloop_fill<<<(NN + TB - 1) / TB, TB>>>();

    // layer 1
    gemm1<<<dim3((NN + 63) / 64, F1 / 32), TB>>>(x, W1, as1, ad1);
    aggregate1<<<(int)(((size_t)NN * 32 + TB - 1) / TB), TB>>>(b1);

    // layer 2
    gemm2<<<dim3((NN + 63) / 64, 1), TB>>>(W2, as2, ad2);
    aggregate2<<<(int)(((size_t)NN * 32 + TB - 1) / TB), TB>>>(out, b2);
}

// round 9
// speedup vs baseline: 1.7658x; 1.0441x over previous
#include <cuda_runtime.h>
#include <cuda_bf16.h>
#include <cstdint>

#define NN 50000
#define EE 800000
#define E2T (EE + NN)
#define IN_F 128
#define ED_F 16
#define F1 128
#define HEADS 4
#define HID 32
#define OUTF 32
#define NEG_SLOPE 0.2f

// ---------------- scratch ----------------
__device__ __align__(16) float g_h1[(size_t)NN * F1];
__device__ __align__(16) float g_hr[(size_t)NN * F1];
__device__ __align__(16) float g_h2[(size_t)NN * OUTF];
__device__ __align__(16) float4 g_saed1[(size_t)E2T];
__device__ float    g_saed2[(size_t)E2T];
__device__ int      g_ssrc[(size_t)E2T];
__device__ int      g_count[NN];
__device__ int      g_rowstart[NN + 1];
__device__ int      g_cursor[NN];
__device__ float    g_asrc1[NN * HEADS], g_adst1[NN * HEADS];
__device__ float    g_asrc2[NN], g_adst2[NN];
__device__ float    g_wae1[ED_F * HEADS];
__device__ float    g_wae2[ED_F];
__device__ float    g_emean[ED_F];
__device__ int      g_is64;

__device__ __forceinline__ void load_edge(const void* eidx, int e, int is64, int& se, int& de) {
    if (is64) {
        const long long* p = (const long long*)eidx;
        se = (int)p[e];
        de = (int)p[(size_t)EE + e];
    } else {
        const int* p = (const int*)eidx;
        se = p[e];
        de = p[EE + e];
    }
}

// ---------------- setup: probe dtype + init counters + prep wae ----------------
__global__ void setup(const void* eidx,
                      const float* __restrict__ We1, const float* __restrict__ ae1,
                      const float* __restrict__ We2, const float* __restrict__ ae2) {
    int i = blockIdx.x * blockDim.x + threadIdx.x;
    if (i < NN) g_count[i] = 0;
    if (i < ED_F) g_emean[i] = 0.f;
    if (blockIdx.x == 0 && threadIdx.x < 32) {
        const int* p = (const int*)eidx;
        int lane = threadIdx.x;
        int allzero = 1;
        #pragma unroll
        for (int k = 0; k < 8; k++)
            if (p[2 * (lane * 8 + k) + 1] != 0) allzero = 0;
        unsigned vote = __ballot_sync(0xffffffffu, allzero);
        if (lane == 0) g_is64 = (vote == 0xffffffffu) ? 1 : 0;
    }
    if (blockIdx.x == 1) {
        int t = threadIdx.x;
        if (t < ED_F * HEADS) {
            int d = t >> 2, h = t & 3;
            float s = 0.f;
            #pragma unroll
            for (int c = 0; c < HID; c++) s += We1[d * F1 + h * HID + c] * ae1[h * HID + c];
            g_wae1[t] = s;
        } else if (t < ED_F * HEADS + ED_F) {
            int d = t - ED_F * HEADS;
            float s = 0.f;
            #pragma unroll
            for (int c = 0; c < OUTF; c++) s += We2[d * OUTF + c] * ae2[c];
            g_wae2[d] = s;
        }
    }
}

// ---------------- CSR count (4 edges/thread) ----------------
__global__ void count_edges(const void* __restrict__ eidx) {
    int base = 4 * (blockIdx.x * blockDim.x + threadIdx.x);
    int is64 = g_is64;
    #pragma unroll
    for (int i = 0; i < 4; i++) {
        int e = base + i;
        if (e < EE) {
            int de;
            if (is64) de = (int)((const long long*)eidx)[(size_t)EE + e];
            else      de = ((const int*)eidx)[EE + e];
            atomicAdd(&g_count[de], 1);
        }
    }
}

// ---------------- CSR scan (single block) ----------------
__global__ void scan_rows() {
    __shared__ int ssum[1024];
    const int CH = (NN + 1023) / 1024;
    int tid = threadIdx.x;
    int base = tid * CH;
    int local = 0;
    #pragma unroll 7
    for (int i = 0; i < CH; i++) {
        int idx = base + i;
        if (idx < NN) local += g_count[idx] + 1;
    }
    ssum[tid] = local;
    __syncthreads();
    for (int o = 1; o < 1024; o <<= 1) {
        int v = (tid >= o) ? ssum[tid - o] : 0;
        __syncthreads();
        ssum[tid] += v;
        __syncthreads();
    }
    int run = (tid == 0) ? 0 : ssum[tid - 1];
    for (int i = 0; i < CH; i++) {
        int idx = base + i;
        if (idx < NN) {
            g_rowstart[idx] = run;
            g_cursor[idx] = run + 1;
            run += g_count[idx] + 1;
        }
    }
    if (tid == 1023) g_rowstart[NN] = run;
}

// ---------------- edge dots + CSR scatter + emean ----------------
__global__ void edge_dots_scatter(const void* __restrict__ eidx, const float* __restrict__ ea) {
    __shared__ float s16[ED_F];
    if (threadIdx.x < ED_F) s16[threadIdx.x] = 0.f;
    __syncthreads();
    int e = blockIdx.x * blockDim.x + threadIdx.x;
    float4 q[4];
    if (e < EE) {
        const float4* eav = reinterpret_cast<const float4*>(ea + (size_t)e * ED_F);
        #pragma unroll
        for (int i = 0; i < 4; i++) q[i] = eav[i];
        float a0 = 0.f, a1 = 0.f, a2 = 0.f, a3 = 0.f, a4 = 0.f;
        #pragma unroll
        for (int i = 0; i < 4; i++) {
            const float* v = &q[i].x;
            #pragma unroll
            for (int j = 0; j < 4; j++) {
                int d = i * 4 + j;
                float vv = v[j];
                a0 += vv * g_wae1[d * HEADS + 0];
                a1 += vv * g_wae1[d * HEADS + 1];
                a2 += vv * g_wae1[d * HEADS + 2];
                a3 += vv * g_wae1[d * HEADS + 3];
                a4 += vv * g_wae2[d];
            }
        }
        int se, de;
        load_edge(eidx, e, g_is64, se, de);
        int pos = atomicAdd(&g_cursor[de], 1);
        g_ssrc[pos] = se;
        g_saed1[pos] = make_float4(a0, a1, a2, a3);
        g_saed2[pos] = a4;
    } else {
        #pragma unroll
        for (int i = 0; i < 4; i++) q[i] = make_float4(0.f, 0.f, 0.f, 0.f);
    }
    #pragma unroll
    for (int o = 16; o; o >>= 1) {
        #pragma unroll
        for (int i = 0; i < 4; i++) {
            q[i].x += __shfl_xor_sync(0xffffffffu, q[i].x, o);
            q[i].y += __shfl_xor_sync(0xffffffffu, q[i].y, o);
            q[i].z += __shfl_xor_sync(0xffffffffu, q[i].z, o);
            q[i].w += __shfl_xor_sync(0xffffffffu, q[i].w, o);
        }
    }
    if ((threadIdx.x & 31) == 0) {
        #pragma unroll
        for (int i = 0; i < 4; i++) {
            atomicAdd(&s16[i * 4 + 0], q[i].x);
            atomicAdd(&s16[i * 4 + 1], q[i].y);
            atomicAdd(&s16[i * 4 + 2], q[i].z);
            atomicAdd(&s16[i * 4 + 3], q[i].w);
        }
    }
    __syncthreads();
    if (threadIdx.x < ED_F) atomicAdd(&g_emean[threadIdx.x], s16[threadIdx.x]);
}

// ---------------- self-loop fill (computes sl consts per block) ----------------
__global__ void selfloop_fill() {
    __shared__ float sl1s[HEADS];
    __shared__ float sl2s;
    int t = threadIdx.x;
    const float inv_e = 1.f / (float)EE;
    if (t < HEADS) {
        float s = 0.f;
        #pragma unroll
        for (int d = 0; d < ED_F; d++) s += g_emean[d] * inv_e * g_wae1[d * HEADS + t];
        sl1s[t] = s;
    } else if (t == HEADS) {
        float s = 0.f;
        #pragma unroll
        for (int d = 0; d < ED_F; d++) s += g_emean[d] * inv_e * g_wae2[d];
        sl2s = s;
    }
    __syncthreads();
    int n = blockIdx.x * blockDim.x + t;
    if (n >= NN) return;
    int j = g_rowstart[n];
    g_ssrc[j] = n;
    g_saed1[j] = make_float4(sl1s[0], sl1s[1], sl1s[2], sl1s[3]);
    g_saed2[j] = sl2s;
}

// ---------------- GEMM1: h1 = x @ W1 (A-tile cached once, 4 col-panels), fused coef1 ----------------
__global__ void gemm1(const float* __restrict__ A, const float* __restrict__ B,
                      const float* __restrict__ as1, const float* __restrict__ ad1) {
    __shared__ float As[64][IN_F + 4];   // 64 x 132
    __shared__ float Bs[IN_F][36];       // 128 x 36 (one 32-col panel)
    int row0 = blockIdx.x * 64;
    int tx = threadIdx.x & 31;
    int ty = threadIdx.x >> 5;
    // load A tile (64 x 128) as float4, coalesced
    {
        const float4* A4 = reinterpret_cast<const float4*>(A);
        #pragma unroll
        for (int i = 0; i < 8; i++) {
            int idx = threadIdx.x + i * 256;
            int r = idx >> 5, c4 = idx & 31;
            int gr = row0 + r;
            float4 v = (gr < NN) ? A4[(size_t)gr * 32 + c4] : make_float4(0.f, 0.f, 0.f, 0.f);
            *reinterpret_cast<float4*>(&As[r][c4 * 4]) = v;
        }
    }
    for (int cb = 0; cb < HEADS; cb++) {
        __syncthreads();
        // load B panel (128 x 32)
        #pragma unroll
        for (int i = 0; i < 16; i++) {
            int idx = threadIdx.x + i * 256;
            int r = idx >> 5, c = idx & 31;
            Bs[r][c] = B[(size_t)r * F1 + cb * 32 + c];
        }
        __syncthreads();
        float acc[8];
        #pragma unroll
        for (int r = 0; r < 8; r++) acc[r] = 0.f;
        #pragma unroll 4
        for (int kk = 0; kk < IN_F; kk++) {
            float bv = Bs[kk][tx];
            #pragma unroll
            for (int r = 0; r < 8; r++) acc[r] += As[ty * 8 + r][kk] * bv;
        }
        float asv = as1[cb * HID + tx];
        float adv = ad1[cb * HID + tx];
        #pragma unroll
        for (int r = 0; r < 8; r++) {
            int gr = row0 + ty * 8 + r;
            if (gr < NN) g_h1[(size_t)gr * F1 + cb * 32 + tx] = acc[r];
            float sv = acc[r] * asv;
            float dv = acc[r] * adv;
            #pragma unroll
            for (int o = 16; o; o >>= 1) {
                sv += __shfl_xor_sync(0xffffffffu, sv, o);
                dv += __shfl_xor_sync(0xffffffffu, dv, o);
            }
            if (tx == 0 && gr < NN) {
                g_asrc1[gr * HEADS + cb] = sv;
                g_adst1[gr * HEADS + cb] = dv;
            }
        }
    }
}

// ---------------- aggregate layer 1: warp/node, 4-edge unroll ----------------
__global__ void aggregate1(const float* __restrict__ b1) {
    int n = (blockIdx.x * blockDim.x + threadIdx.x) >> 5;
    if (n >= NN) return;
    int lane = threadIdx.x & 31;
    int beg = g_rowstart[n];
    int end = g_rowstart[n + 1];
    int h4 = lane & 3;
    float adst = (lane < 16) ? g_adst1[n * HEADS + h4] : 0.f;
    float denp = 0.f;
    float4 acc = make_float4(0.f, 0.f, 0.f, 0.f);
    int hh = lane >> 3;
    int j = beg;
    for (; j + 4 <= end; j += 4) {
        int sK = (lane < 4) ? g_ssrc[j + lane] : 0;
        int s0 = __shfl_sync(0xffffffffu, sK, 0);
        int s1 = __shfl_sync(0xffffffffu, sK, 1);
        int s2 = __shfl_sync(0xffffffffu, sK, 2);
        int s3 = __shfl_sync(0xffffffffu, sK, 3);
        float ex = 0.f;
        if (lane < 16) {
            int k = lane >> 2;
            int sk = (k == 0) ? s0 : (k == 1) ? s1 : (k == 2) ? s2 : s3;
            float aed = ((const float*)&g_saed1[j + k])[h4];
            float lg = g_asrc1[sk * HEADS + h4] + adst + aed;
            lg = (lg > 0.f) ? lg : NEG_SLOPE * lg;
            ex = __expf(lg);
            denp += ex;
        }
        float e0 = __shfl_sync(0xffffffffu, ex, hh);
        float e1 = __shfl_sync(0xffffffffu, ex, 4 + hh);
        float e2 = __shfl_sync(0xffffffffu, ex, 8 + hh);
        float e3 = __shfl_sync(0xffffffffu, ex, 12 + hh);
        float4 v0 = *reinterpret_cast<const float4*>(&g_h1[(size_t)s0 * F1 + lane * 4]);
        float4 v1 = *reinterpret_cast<const float4*>(&g_h1[(size_t)s1 * F1 + lane * 4]);
        float4 v2 = *reinterpret_cast<const float4*>(&g_h1[(size_t)s2 * F1 + lane * 4]);
        float4 v3 = *reinterpret_cast<const float4*>(&g_h1[(size_t)s3 * F1 + lane * 4]);
        acc.x += e0 * v0.x + e1 * v1.x + e2 * v2.x + e3 * v3.x;
        acc.y += e0 * v0.y + e1 * v1.y + e2 * v2.y + e3 * v3.y;
        acc.z += e0 * v0.z + e1 * v1.z + e2 * v2.z + e3 * v3.z;
        acc.w += e0 * v0.w + e1 * v1.w + e2 * v2.w + e3 * v3.w;
    }
    for (; j < end; j++) {
        int se = g_ssrc[j];
        float ex = 0.f;
        if (lane < 4) {
            float aed = ((const float*)&g_saed1[j])[lane];
            float lg = g_asrc1[se * HEADS + lane] + adst + aed;
            lg = (lg > 0.f) ? lg : NEG_SLOPE * lg;
            ex = __expf(lg);
            denp += ex;
        }
        float eb = __shfl_sync(0xffffffffu, ex, hh);
        float4 v = *reinterpret_cast<const float4*>(&g_h1[(size_t)se * F1 + lane * 4]);
        acc.x += eb * v.x;
        acc.y += eb * v.y;
        acc.z += eb * v.z;
        acc.w += eb * v.w;
    }
    float den = __shfl_sync(0xffffffffu, denp, hh)
              + __shfl_sync(0xffffffffu, denp, 4 + hh)
              + __shfl_sync(0xffffffffu, denp, 8 + hh)
              + __shfl_sync(0xffffffffu, denp, 12 + hh);
    float inv = 1.f / (den + 1e-16f);
    float4 bv = *reinterpret_cast<const float4*>(&b1[lane * 4]);
    float4 o;
    o.x = fmaxf(acc.x * inv + bv.x, 0.f);
    o.y = fmaxf(acc.y * inv + bv.y, 0.f);
    o.z = fmaxf(acc.z * inv + bv.z, 0.f);
    o.w = fmaxf(acc.w * inv + bv.w, 0.f);
    *reinterpret_cast<float4*>(&g_hr[(size_t)n * F1 + lane * 4]) = o;
}

// ---------------- GEMM2: h2 = hr @ W2, fused coef2 ----------------
__global__ void gemm2(const float* __restrict__ B,
                      const float* __restrict__ as2, const float* __restrict__ ad2) {
    __shared__ float As[64][33];
    __shared__ float Bs[32][33];
    const int M = NN, K = F1, NC = OUTF;
    int row0 = blockIdx.x * 64;
    int tx = threadIdx.x & 31;
    int ty = threadIdx.x >> 5;
    float acc[8];
    #pragma unroll
    for (int r = 0; r < 8; r++) acc[r] = 0.f;
    for (int k0 = 0; k0 < K; k0 += 32) {
        #pragma unroll
        for (int i = 0; i < 8; i++) {
            int idx = threadIdx.x + i * 256;
            int r = idx >> 5, c = idx & 31;
            int gr = row0 + r;
            As[r][c] = (gr < M) ? g_hr[(size_t)gr * K + k0 + c] : 0.f;
        }
        #pragma unroll
        for (int i = 0; i < 4; i++) {
            int idx = threadIdx.x + i * 256;
            int r = idx >> 5, c = idx & 31;
            Bs[r][c] = B[(size_t)(k0 + r) * NC + c];
        }
        __syncthreads();
        #pragma unroll
        for (int kk = 0; kk < 32; kk++) {
            float bv = Bs[kk][tx];
            #pragma unroll
            for (int r = 0; r < 8; r++) acc[r] += As[ty * 8 + r][kk] * bv;
        }
        __syncthreads();
    }
    float asv = as2[tx];
    float adv = ad2[tx];
    #pragma unroll
    for (int r = 0; r < 8; r++) {
        int gr = row0 + ty * 8 + r;
        if (gr < M) g_h2[(size_t)gr * NC + tx] = acc[r];
        float sv = acc[r] * asv;
        float dv = acc[r] * adv;
        #pragma unroll
        for (int o = 16; o; o >>= 1) {
            sv += __shfl_xor_sync(0xffffffffu, sv, o);
            dv += __shfl_xor_sync(0xffffffffu, dv, o);
        }
        if (tx == 0 && gr < M) {
            g_asrc2[gr] = sv;
            g_adst2[gr] = dv;
        }
    }
}

// ---------------- aggregate layer 2: warp/node, 4-edge unroll ----------------
__global__ void aggregate2(float* __restrict__ out, const float* __restrict__ b2) {
    int n = (blockIdx.x * blockDim.x + threadIdx.x) >> 5;
    if (n >= NN) return;
    int lane = threadIdx.x & 31;
    int beg = g_rowstart[n];
    int end = g_rowstart[n + 1];
    float adst = g_adst2[n];
    float denp = 0.f, acc = 0.f;
    int j = beg;
    for (; j + 4 <= end; j += 4) {
        int sK = (lane < 4) ? g_ssrc[j + lane] : 0;
        float ex = 0.f;
        if (lane < 4) {
            float lg = g_asrc2[sK] + adst + g_saed2[j + lane];
            lg = (lg > 0.f) ? lg : NEG_SLOPE * lg;
            ex = __expf(lg);
            denp += ex;
        }
        int s0 = __shfl_sync(0xffffffffu, sK, 0);
        int s1 = __shfl_sync(0xffffffffu, sK, 1);
        int s2 = __shfl_sync(0xffffffffu, sK, 2);
        int s3 = __shfl_sync(0xffffffffu, sK, 3);
        float e0 = __shfl_sync(0xffffffffu, ex, 0);
        float e1 = __shfl_sync(0xffffffffu, ex, 1);
        float e2 = __shfl_sync(0xffffffffu, ex, 2);
        float e3 = __shfl_sync(0xffffffffu, ex, 3);
        acc += e0 * g_h2[(size_t)s0 * OUTF + lane]
             + e1 * g_h2[(size_t)s1 * OUTF + lane]
             + e2 * g_h2[(size_t)s2 * OUTF + lane]
             + e3 * g_h2[(size_t)s3 * OUTF + lane];
    }
    for (; j < end; j++) {
        int se = g_ssrc[j];
        float ex = 0.f;
        if (lane == 0) {
            float lg = g_asrc2[se] + adst + g_saed2[j];
            lg = (lg > 0.f) ? lg : NEG_SLOPE * lg;
            ex = __expf(lg);
            denp += ex;
        }
        float eb = __shfl_sync(0xffffffffu, ex, 0);
        acc += eb * g_h2[(size_t)se * OUTF + lane];
    }
    float den = __shfl_sync(0xffffffffu, denp, 0)
              + __shfl_sync(0xffffffffu, denp, 1)
              + __shfl_sync(0xffffffffu, denp, 2)
              + __shfl_sync(0xffffffffu, denp, 3);
    out[(size_t)n * OUTF + lane] = acc / (den + 1e-16f) + b2[lane];
}

// ---------------- launch ----------------
extern "C" void kernel_launch(void* const* d_in, const int* in_sizes, int n_in,
                              void* d_out, int out_size) {
    int used[64];
    for (int i = 0; i < n_in && i < 64; i++) used[i] = 0;
    auto take = [&](int want) -> const void* {
        for (int i = 0; i < n_in && i < 64; i++)
            if (!used[i] && in_sizes[i] == want) { used[i] = 1; return d_in[i]; }
        return nullptr;
    };
    const float* x   = (const float*)take(NN * IN_F);
    const void*  eix = take(2 * EE);
    const float* ea  = (const float*)take(EE * ED_F);
    const float* W1  = (const float*)take(IN_F * F1);
    const float* We1 = (const float*)take(ED_F * F1);
    const float* W2  = (const float*)take(F1 * OUTF);
    const float* We2 = (const float*)take(ED_F * OUTF);
    const float* g128[4] = {nullptr, nullptr, nullptr, nullptr};
    const float* g32[4]  = {nullptr, nullptr, nullptr, nullptr};
    int n128 = 0, n32 = 0;
    for (int i = 0; i < n_in && i < 64; i++) {
        if (used[i]) continue;
        if (in_sizes[i] == 128 && n128 < 4) g128[n128++] = (const float*)d_in[i];
        else if (in_sizes[i] == 32 && n32 < 4) g32[n32++] = (const float*)d_in[i];
    }
    const float* as1 = g128[0], *ad1 = g128[1], *ae1 = g128[2], *b1 = g128[3];
    const float* as2 = g32[0],  *ad2 = g32[1],  *ae2 = g32[2],  *b2 = g32[3];
    if (!x || !eix || !ea || !W1 || !We1 || !W2 || !We2 || n128 < 4 || n32 < 4) {
        x   = (const float*)d_in[0];  eix = d_in[1];               ea  = (const float*)d_in[2];
        W1  = (const float*)d_in[3];  We1 = (const float*)d_in[4];
        as1 = (const float*)d_in[5];  ad1 = (const float*)d_in[6]; ae1 = (const float*)d_in[7];
        b1  = (const float*)d_in[8];  W2  = (const float*)d_in[9]; We2 = (const float*)d_in[10];
        as2 = (const float*)d_in[11]; ad2 = (const float*)d_in[12]; ae2 = (const float*)d_in[13];
        b2  = (const float*)d_in[14];
    }
    float* out = (float*)d_out;

    const int TB = 256;

    setup<<<(NN + TB - 1) / TB, TB>>>(eix, We1, ae1, We2, ae2);
    count_edges<<<(EE + TB * 4 - 1) / (TB * 4), TB>>>(eix);
    scan_rows<<<1, 1024>>>();
    edge_dots_scatter<<<(EE + TB - 1) / TB, TB>>>(eix, ea);
    selfloop_fill<<<(NN + TB - 1) / TB, TB>>>();

    gemm1<<<(NN + 63) / 64, TB>>>(x, W1, as1, ad1);
    aggregate1<<<(int)(((size_t)NN * 32 + TB - 1) / TB), TB>>>(b1);

    gemm2<<<(NN + 63) / 64, TB>>>(W2, as2, ad2);
    aggregate2<<<(int)(((size_t)NN * 32 + TB - 1) / TB), TB>>>(out, b2);
}

// round 11
// speedup vs baseline: 2.2535x; 1.2762x over previous
#include <cuda_runtime.h>
#include <cuda_bf16.h>
#include <cstdint>

#define NN 50000
#define EE 800000
#define E2T (EE + NN)
#define IN_F 128
#define ED_F 16
#define F1 128
#define HEADS 4
#define HID 32
#define OUTF 32
#define NEG_SLOPE 0.2f

// ---------------- scratch ----------------
__device__ __align__(16) float g_h1[(size_t)NN * F1];
__device__ __align__(16) float g_hr[(size_t)NN * F1];
__device__ __align__(16) float g_h2[(size_t)NN * OUTF];
__device__ __align__(16) float4 g_saed1[(size_t)E2T];   // per-edge head dots (sorted)
__device__ __align__(8)  float2 g_sb[(size_t)E2T];      // (aed2, src bits)
__device__ int      g_count[NN];                        // in-degree
__device__ int      g_rowstart[NN];
__device__ int      g_cursor[NN];
__device__ int      g_total;
__device__ float    g_asrc1[NN * HEADS], g_adst1[NN * HEADS];
__device__ float    g_asrc2[NN], g_adst2[NN];
__device__ float    g_wae1[ED_F * HEADS];
__device__ float    g_wae2[ED_F];
__device__ float    g_emean[ED_F];
__device__ int      g_is64;

__device__ __forceinline__ void load_edge(const void* eidx, int e, int is64, int& se, int& de) {
    if (is64) {
        const long long* p = (const long long*)eidx;
        se = (int)p[e];
        de = (int)p[(size_t)EE + e];
    } else {
        const int* p = (const int*)eidx;
        se = p[e];
        de = p[EE + e];
    }
}

__device__ __forceinline__ unsigned long long fma2(unsigned long long a, unsigned long long b,
                                                   unsigned long long c) {
    unsigned long long d;
    asm("fma.rn.f32x2 %0, %1, %2, %3;" : "=l"(d) : "l"(a), "l"(b), "l"(c));
    return d;
}
__device__ __forceinline__ float pairsum(unsigned long long v) {
    float lo, hi;
    asm("mov.b64 {%0, %1}, %2;" : "=f"(lo), "=f"(hi) : "l"(v));
    return lo + hi;
}

// ---------------- setup ----------------
__global__ void setup(const void* eidx,
                      const float* __restrict__ We1, const float* __restrict__ ae1,
                      const float* __restrict__ We2, const float* __restrict__ ae2) {
    int i = blockIdx.x * blockDim.x + threadIdx.x;
    if (i < NN) g_count[i] = 0;
    if (i < ED_F) g_emean[i] = 0.f;
    if (i == 0) g_total = 0;
    if (blockIdx.x == 0 && threadIdx.x < 32) {
        const int* p = (const int*)eidx;
        int lane = threadIdx.x;
        int allzero = 1;
        #pragma unroll
        for (int k = 0; k < 8; k++)
            if (p[2 * (lane * 8 + k) + 1] != 0) allzero = 0;
        unsigned vote = __ballot_sync(0xffffffffu, allzero);
        if (lane == 0) g_is64 = (vote == 0xffffffffu) ? 1 : 0;
    }
    if (blockIdx.x == 1) {
        int t = threadIdx.x;
        if (t < ED_F * HEADS) {
            int d = t >> 2, h = t & 3;
            float s = 0.f;
            #pragma unroll
            for (int c = 0; c < HID; c++) s += We1[d * F1 + h * HID + c] * ae1[h * HID + c];
            g_wae1[t] = s;
        } else if (t < ED_F * HEADS + ED_F) {
            int d = t - ED_F * HEADS;
            float s = 0.f;
            #pragma unroll
            for (int c = 0; c < OUTF; c++) s += We2[d * OUTF + c] * ae2[c];
            g_wae2[d] = s;
        }
    }
}

// ---------------- CSR count ----------------
__global__ void count_edges(const void* __restrict__ eidx) {
    int base = 4 * (blockIdx.x * blockDim.x + threadIdx.x);
    int is64 = g_is64;
    #pragma unroll
    for (int i = 0; i < 4; i++) {
        int e = base + i;
        if (e < EE) {
            int de;
            if (is64) de = (int)((const long long*)eidx)[(size_t)EE + e];
            else      de = ((const int*)eidx)[EE + e];
            atomicAdd(&g_count[de], 1);
        }
    }
}

// ---------------- parallel segment assignment (order-free CSR) ----------------
__global__ void assign_rows() {
    __shared__ int sh[256];
    __shared__ int sbase;
    int tid = threadIdx.x;
    int n = blockIdx.x * 256 + tid;
    int deg = (n < NN) ? g_count[n] + 1 : 0;
    sh[tid] = deg;
    __syncthreads();
    #pragma unroll
    for (int o = 1; o < 256; o <<= 1) {
        int v = (tid >= o) ? sh[tid - o] : 0;
        __syncthreads();
        sh[tid] += v;
        __syncthreads();
    }
    int incl = sh[tid];
    if (tid == 255) sbase = atomicAdd(&g_total, incl);
    __syncthreads();
    if (n < NN) {
        int rs = sbase + incl - deg;
        g_rowstart[n] = rs;
        g_cursor[n] = rs + 1;   // slot 0 reserved for self-loop
    }
}

// ---------------- edge dots + CSR scatter + emean ----------------
__global__ void edge_dots_scatter(const void* __restrict__ eidx, const float* __restrict__ ea) {
    __shared__ float s16[ED_F];
    if (threadIdx.x < ED_F) s16[threadIdx.x] = 0.f;
    __syncthreads();
    int e = blockIdx.x * blockDim.x + threadIdx.x;
    float4 q[4];
    if (e < EE) {
        const float4* eav = reinterpret_cast<const float4*>(ea + (size_t)e * ED_F);
        #pragma unroll
        for (int i = 0; i < 4; i++) q[i] = eav[i];
        float a0 = 0.f, a1 = 0.f, a2 = 0.f, a3 = 0.f, a4 = 0.f;
        #pragma unroll
        for (int i = 0; i < 4; i++) {
            const float* v = &q[i].x;
            #pragma unroll
            for (int j = 0; j < 4; j++) {
                int d = i * 4 + j;
                float vv = v[j];
                a0 += vv * g_wae1[d * HEADS + 0];
                a1 += vv * g_wae1[d * HEADS + 1];
                a2 += vv * g_wae1[d * HEADS + 2];
                a3 += vv * g_wae1[d * HEADS + 3];
                a4 += vv * g_wae2[d];
            }
        }
        int se, de;
        load_edge(eidx, e, g_is64, se, de);
        int pos = atomicAdd(&g_cursor[de], 1);
        g_saed1[pos] = make_float4(a0, a1, a2, a3);
        g_sb[pos] = make_float2(a4, __int_as_float(se));
    } else {
        #pragma unroll
        for (int i = 0; i < 4; i++) q[i] = make_float4(0.f, 0.f, 0.f, 0.f);
    }
    #pragma unroll
    for (int o = 16; o; o >>= 1) {
        #pragma unroll
        for (int i = 0; i < 4; i++) {
            q[i].x += __shfl_xor_sync(0xffffffffu, q[i].x, o);
            q[i].y += __shfl_xor_sync(0xffffffffu, q[i].y, o);
            q[i].z += __shfl_xor_sync(0xffffffffu, q[i].z, o);
            q[i].w += __shfl_xor_sync(0xffffffffu, q[i].w, o);
        }
    }
    if ((threadIdx.x & 31) == 0) {
        #pragma unroll
        for (int i = 0; i < 4; i++) {
            atomicAdd(&s16[i * 4 + 0], q[i].x);
            atomicAdd(&s16[i * 4 + 1], q[i].y);
            atomicAdd(&s16[i * 4 + 2], q[i].z);
            atomicAdd(&s16[i * 4 + 3], q[i].w);
        }
    }
    __syncthreads();
    if (threadIdx.x < ED_F) atomicAdd(&g_emean[threadIdx.x], s16[threadIdx.x]);
}

// ---------------- self-loop fill ----------------
__global__ void selfloop_fill() {
    __shared__ float sl1s[HEADS];
    __shared__ float sl2s;
    int t = threadIdx.x;
    const float inv_e = 1.f / (float)EE;
    if (t < HEADS) {
        float s = 0.f;
        #pragma unroll
        for (int d = 0; d < ED_F; d++) s += g_emean[d] * inv_e * g_wae1[d * HEADS + t];
        sl1s[t] = s;
    } else if (t == HEADS) {
        float s = 0.f;
        #pragma unroll
        for (int d = 0; d < ED_F; d++) s += g_emean[d] * inv_e * g_wae2[d];
        sl2s = s;
    }
    __syncthreads();
    int n = blockIdx.x * blockDim.x + t;
    if (n >= NN) return;
    int j = g_rowstart[n];
    g_saed1[j] = make_float4(sl1s[0], sl1s[1], sl1s[2], sl1s[3]);
    g_sb[j] = make_float2(sl2s, __int_as_float(n));
}

// ---------------- GEMM1 (FFMA2 kk-pairs): h1 = x @ W1, fused coef1 ----------------
__global__ void gemm1(const float* __restrict__ A, const float* __restrict__ B,
                      const float* __restrict__ as1, const float* __restrict__ ad1) {
    __shared__ float As[64][IN_F + 4];   // stride 132 floats = 528 B: 16B- and 8B-aligned rows
    __shared__ float Bst[32][IN_F + 4];  // cols x kk transposed
    int row0 = blockIdx.x * 64;
    int tx = threadIdx.x & 31;
    int ty = threadIdx.x >> 5;
    {
        const float4* A4 = reinterpret_cast<const float4*>(A);
        #pragma unroll
        for (int i = 0; i < 8; i++) {
            int idx = threadIdx.x + i * 256;
            int r = idx >> 5, c4 = idx & 31;
            int gr = row0 + r;
            float4 v = (gr < NN) ? A4[(size_t)gr * 32 + c4] : make_float4(0.f, 0.f, 0.f, 0.f);
            *reinterpret_cast<float4*>(&As[r][c4 * 4]) = v;
        }
    }
    for (int cb = 0; cb < HEADS; cb++) {
        __syncthreads();
        #pragma unroll
        for (int i = 0; i < 16; i++) {
            int idx = threadIdx.x + i * 256;
            int r = idx >> 5, c = idx & 31;   // r = kk, c = col
            Bst[c][r] = B[(size_t)r * F1 + cb * 32 + c];
        }
        __syncthreads();
        unsigned long long acc2[8];
        #pragma unroll
        for (int r = 0; r < 8; r++) acc2[r] = 0ull;
        #pragma unroll 4
        for (int k2 = 0; k2 < IN_F / 2; k2++) {
            unsigned long long bv = *reinterpret_cast<const unsigned long long*>(&Bst[tx][k2 * 2]);
            #pragma unroll
            for (int r = 0; r < 8; r++) {
                unsigned long long av =
                    *reinterpret_cast<const unsigned long long*>(&As[ty * 8 + r][k2 * 2]);
                acc2[r] = fma2(av, bv, acc2[r]);
            }
        }
        float asv = as1[cb * HID + tx];
        float adv = ad1[cb * HID + tx];
        #pragma unroll
        for (int r = 0; r < 8; r++) {
            float acc = pairsum(acc2[r]);
            int gr = row0 + ty * 8 + r;
            if (gr < NN) g_h1[(size_t)gr * F1 + cb * 32 + tx] = acc;
            float sv = acc * asv;
            float dv = acc * adv;
            #pragma unroll
            for (int o = 16; o; o >>= 1) {
                sv += __shfl_xor_sync(0xffffffffu, sv, o);
                dv += __shfl_xor_sync(0xffffffffu, dv, o);
            }
            if (tx == 0 && gr < NN) {
                g_asrc1[gr * HEADS + cb] = sv;
                g_adst1[gr * HEADS + cb] = dv;
            }
        }
    }
}

// ---------------- aggregate layer 1 ----------------
__global__ void aggregate1(const float* __restrict__ b1) {
    int n = (blockIdx.x * blockDim.x + threadIdx.x) >> 5;
    if (n >= NN) return;
    int lane = threadIdx.x & 31;
    int beg = g_rowstart[n];
    int end = beg + g_count[n] + 1;
    int h4 = lane & 3;
    float adst = (lane < 16) ? g_adst1[n * HEADS + h4] : 0.f;
    float denp = 0.f;
    float4 acc = make_float4(0.f, 0.f, 0.f, 0.f);
    int hh = lane >> 3;
    int j = beg;
    for (; j + 4 <= end; j += 4) {
        int sK = (lane < 4) ? __float_as_int(g_sb[j + lane].y) : 0;
        int s0 = __shfl_sync(0xffffffffu, sK, 0);
        int s1 = __shfl_sync(0xffffffffu, sK, 1);
        int s2 = __shfl_sync(0xffffffffu, sK, 2);
        int s3 = __shfl_sync(0xffffffffu, sK, 3);
        float ex = 0.f;
        if (lane < 16) {
            int k = lane >> 2;
            int sk = (k == 0) ? s0 : (k == 1) ? s1 : (k == 2) ? s2 : s3;
            float aed = ((const float*)&g_saed1[j + k])[h4];
            float lg = g_asrc1[sk * HEADS + h4] + adst + aed;
            lg = (lg > 0.f) ? lg : NEG_SLOPE * lg;
            ex = __expf(lg);
            denp += ex;
        }
        float e0 = __shfl_sync(0xffffffffu, ex, hh);
        float e1 = __shfl_sync(0xffffffffu, ex, 4 + hh);
        float e2 = __shfl_sync(0xffffffffu, ex, 8 + hh);
        float e3 = __shfl_sync(0xffffffffu, ex, 12 + hh);
        float4 v0 = *reinterpret_cast<const float4*>(&g_h1[(size_t)s0 * F1 + lane * 4]);
        float4 v1 = *reinterpret_cast<const float4*>(&g_h1[(size_t)s1 * F1 + lane * 4]);
        float4 v2 = *reinterpret_cast<const float4*>(&g_h1[(size_t)s2 * F1 + lane * 4]);
        float4 v3 = *reinterpret_cast<const float4*>(&g_h1[(size_t)s3 * F1 + lane * 4]);
        acc.x += e0 * v0.x + e1 * v1.x + e2 * v2.x + e3 * v3.x;
        acc.y += e0 * v0.y + e1 * v1.y + e2 * v2.y + e3 * v3.y;
        acc.z += e0 * v0.z + e1 * v1.z + e2 * v2.z + e3 * v3.z;
        acc.w += e0 * v0.w + e1 * v1.w + e2 * v2.w + e3 * v3.w;
    }
    for (; j < end; j++) {
        float2 sb = g_sb[j];
        int se = __float_as_int(sb.y);
        float ex = 0.f;
        if (lane < 4) {
            float aed = ((const float*)&g_saed1[j])[lane];
            float lg = g_asrc1[se * HEADS + lane] + adst + aed;
            lg = (lg > 0.f) ? lg : NEG_SLOPE * lg;
            ex = __expf(lg);
            denp += ex;
        }
        float eb = __shfl_sync(0xffffffffu, ex, hh);
        float4 v = *reinterpret_cast<const float4*>(&g_h1[(size_t)se * F1 + lane * 4]);
        acc.x += eb * v.x;
        acc.y += eb * v.y;
        acc.z += eb * v.z;
        acc.w += eb * v.w;
    }
    float den = __shfl_sync(0xffffffffu, denp, hh)
              + __shfl_sync(0xffffffffu, denp, 4 + hh)
              + __shfl_sync(0xffffffffu, denp, 8 + hh)
              + __shfl_sync(0xffffffffu, denp, 12 + hh);
    float inv = 1.f / (den + 1e-16f);
    float4 bv = *reinterpret_cast<const float4*>(&b1[lane * 4]);
    float4 o;
    o.x = fmaxf(acc.x * inv + bv.x, 0.f);
    o.y = fmaxf(acc.y * inv + bv.y, 0.f);
    o.z = fmaxf(acc.z * inv + bv.z, 0.f);
    o.w = fmaxf(acc.w * inv + bv.w, 0.f);
    *reinterpret_cast<float4*>(&g_hr[(size_t)n * F1 + lane * 4]) = o;
}

// ---------------- GEMM2 (FFMA2 kk-pairs): h2 = hr @ W2, fused coef2 ----------------
__global__ void gemm2(const float* __restrict__ B,
                      const float* __restrict__ as2, const float* __restrict__ ad2) {
    __shared__ float As[64][F1 + 4];
    __shared__ float Bst[32][F1 + 4];
    int row0 = blockIdx.x * 64;
    int tx = threadIdx.x & 31;
    int ty = threadIdx.x >> 5;
    {
        const float4* A4 = reinterpret_cast<const float4*>(g_hr);
        #pragma unroll
        for (int i = 0; i < 8; i++) {
            int idx = threadIdx.x + i * 256;
            int r = idx >> 5, c4 = idx & 31;
            int gr = row0 + r;
            float4 v = (gr < NN) ? A4[(size_t)gr * 32 + c4] : make_float4(0.f, 0.f, 0.f, 0.f);
            *reinterpret_cast<float4*>(&As[r][c4 * 4]) = v;
        }
    }
    #pragma unroll
    for (int i = 0; i < 16; i++) {
        int idx = threadIdx.x + i * 256;
        int r = idx >> 5, c = idx & 31;   // r = kk, c = col
        Bst[c][r] = B[(size_t)r * OUTF + c];
    }
    __syncthreads();
    unsigned long long acc2[8];
    #pragma unroll
    for (int r = 0; r < 8; r++) acc2[r] = 0ull;
    #pragma unroll 4
    for (int k2 = 0; k2 < F1 / 2; k2++) {
        unsigned long long bv = *reinterpret_cast<const unsigned long long*>(&Bst[tx][k2 * 2]);
        #pragma unroll
        for (int r = 0; r < 8; r++) {
            unsigned long long av =
                *reinterpret_cast<const unsigned long long*>(&As[ty * 8 + r][k2 * 2]);
            acc2[r] = fma2(av, bv, acc2[r]);
        }
    }
    float asv = as2[tx];
    float adv = ad2[tx];
    #pragma unroll
    for (int r = 0; r < 8; r++) {
        float acc = pairsum(acc2[r]);
        int gr = row0 + ty * 8 + r;
        if (gr < NN) g_h2[(size_t)gr * OUTF + tx] = acc;
        float sv = acc * asv;
        float dv = acc * adv;
        #pragma unroll
        for (int o = 16; o; o >>= 1) {
            sv += __shfl_xor_sync(0xffffffffu, sv, o);
            dv += __shfl_xor_sync(0xffffffffu, dv, o);
        }
        if (tx == 0 && gr < NN) {
            g_asrc2[gr] = sv;
            g_adst2[gr] = dv;
        }
    }
}

// ---------------- aggregate layer 2 ----------------
__global__ void aggregate2(float* __restrict__ out, const float* __restrict__ b2) {
    int n = (blockIdx.x * blockDim.x + threadIdx.x) >> 5;
    if (n >= NN) return;
    int lane = threadIdx.x & 31;
    int beg = g_rowstart[n];
    int end = beg + g_count[n] + 1;
    float adst = g_adst2[n];
    float denp = 0.f, acc = 0.f;
    int j = beg;
    for (; j + 4 <= end; j += 4) {
        int sK = 0;
        float ex = 0.f;
        if (lane < 4) {
            float2 sbv = g_sb[j + lane];
            sK = __float_as_int(sbv.y);
            float lg = g_asrc2[sK] + adst + sbv.x;
            lg = (lg > 0.f) ? lg : NEG_SLOPE * lg;
            ex = __expf(lg);
            denp += ex;
        }
        int s0 = __shfl_sync(0xffffffffu, sK, 0);
        int s1 = __shfl_sync(0xffffffffu, sK, 1);
        int s2 = __shfl_sync(0xffffffffu, sK, 2);
        int s3 = __shfl_sync(0xffffffffu, sK, 3);
        float e0 = __shfl_sync(0xffffffffu, ex, 0);
        float e1 = __shfl_sync(0xffffffffu, ex, 1);
        float e2 = __shfl_sync(0xffffffffu, ex, 2);
        float e3 = __shfl_sync(0xffffffffu, ex, 3);
        acc += e0 * g_h2[(size_t)s0 * OUTF + lane]
             + e1 * g_h2[(size_t)s1 * OUTF + lane]
             + e2 * g_h2[(size_t)s2 * OUTF + lane]
             + e3 * g_h2[(size_t)s3 * OUTF + lane];
    }
    for (; j < end; j++) {
        float2 sb = g_sb[j];
        int se = __float_as_int(sb.y);
        float ex = 0.f;
        if (lane == 0) {
            float lg = g_asrc2[se] + adst + sb.x;
            lg = (lg > 0.f) ? lg : NEG_SLOPE * lg;
            ex = __expf(lg);
            denp += ex;
        }
        float eb = __shfl_sync(0xffffffffu, ex, 0);
        acc += eb * g_h2[(size_t)se * OUTF + lane];
    }
    float den = __shfl_sync(0xffffffffu, denp, 0)
              + __shfl_sync(0xffffffffu, denp, 1)
              + __shfl_sync(0xffffffffu, denp, 2)
              + __shfl_sync(0xffffffffu, denp, 3);
    out[(size_t)n * OUTF + lane] = acc / (den + 1e-16f) + b2[lane];
}

// ---------------- launch ----------------
extern "C" void kernel_launch(void* const* d_in, const int* in_sizes, int n_in,
                              void* d_out, int out_size) {
    int used[64];
    for (int i = 0; i < n_in && i < 64; i++) used[i] = 0;
    auto take = [&](int want) -> const void* {
        for (int i = 0; i < n_in && i < 64; i++)
            if (!used[i] && in_sizes[i] == want) { used[i] = 1; return d_in[i]; }
        return nullptr;
    };
    const float* x   = (const float*)take(NN * IN_F);
    const void*  eix = take(2 * EE);
    const float* ea  = (const float*)take(EE * ED_F);
    const float* W1  = (const float*)take(IN_F * F1);
    const float* We1 = (const float*)take(ED_F * F1);
    const float* W2  = (const float*)take(F1 * OUTF);
    const float* We2 = (const float*)take(ED_F * OUTF);
    const float* g128[4] = {nullptr, nullptr, nullptr, nullptr};
    const float* g32[4]  = {nullptr, nullptr, nullptr, nullptr};
    int n128 = 0, n32 = 0;
    for (int i = 0; i < n_in && i < 64; i++) {
        if (used[i]) continue;
        if (in_sizes[i] == 128 && n128 < 4) g128[n128++] = (const float*)d_in[i];
        else if (in_sizes[i] == 32 && n32 < 4) g32[n32++] = (const float*)d_in[i];
    }
    const float* as1 = g128[0], *ad1 = g128[1], *ae1 = g128[2], *b1 = g128[3];
    const float* as2 = g32[0],  *ad2 = g32[1],  *ae2 = g32[2],  *b2 = g32[3];
    if (!x || !eix || !ea || !W1 || !We1 || !W2 || !We2 || n128 < 4 || n32 < 4) {
        x   = (const float*)d_in[0];  eix = d_in[1];               ea  = (const float*)d_in[2];
        W1  = (const float*)d_in[3];  We1 = (const float*)d_in[4];
        as1 = (const float*)d_in[5];  ad1 = (const float*)d_in[6]; ae1 = (const float*)d_in[7];
        b1  = (const float*)d_in[8];  W2  = (const float*)d_in[9]; We2 = (const float*)d_in[10];
        as2 = (const float*)d_in[11]; ad2 = (const float*)d_in[12]; ae2 = (const float*)d_in[13];
        b2  = (const float*)d_in[14];
    }
    float* out = (float*)d_out;

    const int TB = 256;

    setup<<<(NN + TB - 1) / TB, TB>>>(eix, We1, ae1, We2, ae2);
    count_edges<<<(EE + TB * 4 - 1) / (TB * 4), TB>>>(eix);
    assign_rows<<<(NN + TB - 1) / TB, TB>>>();
    edge_dots_scatter<<<(EE + TB - 1) / TB, TB>>>(eix, ea);
    selfloop_fill<<<(NN + TB - 1) / TB, TB>>>();

    gemm1<<<(NN + 63) / 64, TB>>>(x, W1, as1, ad1);
    aggregate1<<<(int)(((size_t)NN * 32 + TB - 1) / TB), TB>>>(b1);

    gemm2<<<(NN + 63) / 64, TB>>>(W2, as2, ad2);
    aggregate2<<<(int)(((size_t)NN * 32 + TB - 1) / TB), TB>>>(out, b2);
}

// round 12
// speedup vs baseline: 2.4050x; 1.0672x over previous
#include <cuda_runtime.h>
#include <cuda_fp16.h>
#include <cstdint>

#define NN 50000
#define EE 800000
#define E2T (EE + NN)
#define IN_F 128
#define ED_F 16
#define F1 128
#define HEADS 4
#define HID 32
#define OUTF 32
#define NEG_SLOPE 0.2f

// ---------------- scratch ----------------
__device__ __align__(16) __half g_h1h[(size_t)NN * F1];  // layer1 features (fp16, gather source)
__device__ __align__(16) float g_hr[(size_t)NN * F1];    // layer1 aggregated+relu (fp32)
__device__ __align__(16) float g_h2[(size_t)NN * OUTF];
__device__ __align__(16) float4 g_saed1[(size_t)E2T];
__device__ __align__(8)  float2 g_sb[(size_t)E2T];       // (aed2, src bits)
__device__ int      g_count[NN];
__device__ int      g_rowstart[NN];
__device__ int      g_cursor[NN];
__device__ int      g_total;
__device__ float    g_asrc1[NN * HEADS], g_adst1[NN * HEADS];
__device__ float    g_asrc2[NN], g_adst2[NN];
__device__ float    g_wae1[ED_F * HEADS];
__device__ float    g_wae2[ED_F];
__device__ float    g_emean[ED_F];
__device__ int      g_is64;

__device__ __forceinline__ void load_edge(const void* eidx, int e, int is64, int& se, int& de) {
    if (is64) {
        const long long* p = (const long long*)eidx;
        se = (int)p[e];
        de = (int)p[(size_t)EE + e];
    } else {
        const int* p = (const int*)eidx;
        se = p[e];
        de = p[EE + e];
    }
}

__device__ __forceinline__ unsigned long long fma2(unsigned long long a, unsigned long long b,
                                                   unsigned long long c) {
    unsigned long long d;
    asm("fma.rn.f32x2 %0, %1, %2, %3;" : "=l"(d) : "l"(a), "l"(b), "l"(c));
    return d;
}
__device__ __forceinline__ float pairsum(unsigned long long v) {
    float lo, hi;
    asm("mov.b64 {%0, %1}, %2;" : "=f"(lo), "=f"(hi) : "l"(v));
    return lo + hi;
}
// gather 4 halves (8B) -> float4
__device__ __forceinline__ float4 gather_h4(const __half* p) {
    uint2 u = *reinterpret_cast<const uint2*>(p);
    __half2 a = *reinterpret_cast<__half2*>(&u.x);
    __half2 b = *reinterpret_cast<__half2*>(&u.y);
    float2 fa = __half22float2(a);
    float2 fb = __half22float2(b);
    return make_float4(fa.x, fa.y, fb.x, fb.y);
}

// ---------------- setup ----------------
__global__ void setup(const void* eidx,
                      const float* __restrict__ We1, const float* __restrict__ ae1,
                      const float* __restrict__ We2, const float* __restrict__ ae2) {
    int i = blockIdx.x * blockDim.x + threadIdx.x;
    if (i < NN) g_count[i] = 0;
    if (i < ED_F) g_emean[i] = 0.f;
    if (i == 0) g_total = 0;
    if (blockIdx.x == 0 && threadIdx.x < 32) {
        const int* p = (const int*)eidx;
        int lane = threadIdx.x;
        int allzero = 1;
        #pragma unroll
        for (int k = 0; k < 8; k++)
            if (p[2 * (lane * 8 + k) + 1] != 0) allzero = 0;
        unsigned vote = __ballot_sync(0xffffffffu, allzero);
        if (lane == 0) g_is64 = (vote == 0xffffffffu) ? 1 : 0;
    }
    if (blockIdx.x == 1) {
        int t = threadIdx.x;
        if (t < ED_F * HEADS) {
            int d = t >> 2, h = t & 3;
            float s = 0.f;
            #pragma unroll
            for (int c = 0; c < HID; c++) s += We1[d * F1 + h * HID + c] * ae1[h * HID + c];
            g_wae1[t] = s;
        } else if (t < ED_F * HEADS + ED_F) {
            int d = t - ED_F * HEADS;
            float s = 0.f;
            #pragma unroll
            for (int c = 0; c < OUTF; c++) s += We2[d * OUTF + c] * ae2[c];
            g_wae2[d] = s;
        }
    }
}

// ---------------- CSR count ----------------
__global__ void count_edges(const void* __restrict__ eidx) {
    int base = 4 * (blockIdx.x * blockDim.x + threadIdx.x);
    int is64 = g_is64;
    #pragma unroll
    for (int i = 0; i < 4; i++) {
        int e = base + i;
        if (e < EE) {
            int de;
            if (is64) de = (int)((const long long*)eidx)[(size_t)EE + e];
            else      de = ((const int*)eidx)[EE + e];
            atomicAdd(&g_count[de], 1);
        }
    }
}

// ---------------- parallel segment assignment ----------------
__global__ void assign_rows() {
    __shared__ int sh[256];
    __shared__ int sbase;
    int tid = threadIdx.x;
    int n = blockIdx.x * 256 + tid;
    int deg = (n < NN) ? g_count[n] + 1 : 0;
    sh[tid] = deg;
    __syncthreads();
    #pragma unroll
    for (int o = 1; o < 256; o <<= 1) {
        int v = (tid >= o) ? sh[tid - o] : 0;
        __syncthreads();
        sh[tid] += v;
        __syncthreads();
    }
    int incl = sh[tid];
    if (tid == 255) sbase = atomicAdd(&g_total, incl);
    __syncthreads();
    if (n < NN) {
        int rs = sbase + incl - deg;
        g_rowstart[n] = rs;
        g_cursor[n] = rs + 1;
    }
}

// ---------------- edge dots + CSR scatter + emean (wae staged in smem) ----------------
__global__ void edge_dots_scatter(const void* __restrict__ eidx, const float* __restrict__ ea) {
    __shared__ float4 swae1[ED_F];
    __shared__ float  swae2[ED_F];
    __shared__ float  s16[ED_F];
    if (threadIdx.x < ED_F) {
        swae1[threadIdx.x] = *reinterpret_cast<const float4*>(&g_wae1[threadIdx.x * HEADS]);
        swae2[threadIdx.x] = g_wae2[threadIdx.x];
        s16[threadIdx.x] = 0.f;
    }
    __syncthreads();
    int e = blockIdx.x * blockDim.x + threadIdx.x;
    float4 q[4];
    if (e < EE) {
        const float4* eav = reinterpret_cast<const float4*>(ea + (size_t)e * ED_F);
        #pragma unroll
        for (int i = 0; i < 4; i++) q[i] = eav[i];
        float a0 = 0.f, a1 = 0.f, a2 = 0.f, a3 = 0.f, a4 = 0.f;
        #pragma unroll
        for (int i = 0; i < 4; i++) {
            const float* v = &q[i].x;
            #pragma unroll
            for (int j = 0; j < 4; j++) {
                int d = i * 4 + j;
                float vv = v[j];
                float4 w = swae1[d];
                a0 += vv * w.x;
                a1 += vv * w.y;
                a2 += vv * w.z;
                a3 += vv * w.w;
                a4 += vv * swae2[d];
            }
        }
        int se, de;
        load_edge(eidx, e, g_is64, se, de);
        int pos = atomicAdd(&g_cursor[de], 1);
        g_saed1[pos] = make_float4(a0, a1, a2, a3);
        g_sb[pos] = make_float2(a4, __int_as_float(se));
    } else {
        #pragma unroll
        for (int i = 0; i < 4; i++) q[i] = make_float4(0.f, 0.f, 0.f, 0.f);
    }
    #pragma unroll
    for (int o = 16; o; o >>= 1) {
        #pragma unroll
        for (int i = 0; i < 4; i++) {
            q[i].x += __shfl_xor_sync(0xffffffffu, q[i].x, o);
            q[i].y += __shfl_xor_sync(0xffffffffu, q[i].y, o);
            q[i].z += __shfl_xor_sync(0xffffffffu, q[i].z, o);
            q[i].w += __shfl_xor_sync(0xffffffffu, q[i].w, o);
        }
    }
    if ((threadIdx.x & 31) == 0) {
        #pragma unroll
        for (int i = 0; i < 4; i++) {
            atomicAdd(&s16[i * 4 + 0], q[i].x);
            atomicAdd(&s16[i * 4 + 1], q[i].y);
            atomicAdd(&s16[i * 4 + 2], q[i].z);
            atomicAdd(&s16[i * 4 + 3], q[i].w);
        }
    }
    __syncthreads();
    if (threadIdx.x < ED_F) atomicAdd(&g_emean[threadIdx.x], s16[threadIdx.x]);
}

// ---------------- self-loop fill ----------------
__global__ void selfloop_fill() {
    __shared__ float sl1s[HEADS];
    __shared__ float sl2s;
    int t = threadIdx.x;
    const float inv_e = 1.f / (float)EE;
    if (t < HEADS) {
        float s = 0.f;
        #pragma unroll
        for (int d = 0; d < ED_F; d++) s += g_emean[d] * inv_e * g_wae1[d * HEADS + t];
        sl1s[t] = s;
    } else if (t == HEADS) {
        float s = 0.f;
        #pragma unroll
        for (int d = 0; d < ED_F; d++) s += g_emean[d] * inv_e * g_wae2[d];
        sl2s = s;
    }
    __syncthreads();
    int n = blockIdx.x * blockDim.x + t;
    if (n >= NN) return;
    int j = g_rowstart[n];
    g_saed1[j] = make_float4(sl1s[0], sl1s[1], sl1s[2], sl1s[3]);
    g_sb[j] = make_float2(sl2s, __int_as_float(n));
}

// ---------------- GEMM1 (FFMA2): h1(fp16) = x @ W1, fused coef1 ----------------
__global__ void gemm1(const float* __restrict__ A, const float* __restrict__ B,
                      const float* __restrict__ as1, const float* __restrict__ ad1) {
    __shared__ float As[64][IN_F + 4];
    __shared__ float Bst[32][IN_F + 4];
    int row0 = blockIdx.x * 64;
    int tx = threadIdx.x & 31;
    int ty = threadIdx.x >> 5;
    {
        const float4* A4 = reinterpret_cast<const float4*>(A);
        #pragma unroll
        for (int i = 0; i < 8; i++) {
            int idx = threadIdx.x + i * 256;
            int r = idx >> 5, c4 = idx & 31;
            int gr = row0 + r;
            float4 v = (gr < NN) ? A4[(size_t)gr * 32 + c4] : make_float4(0.f, 0.f, 0.f, 0.f);
            *reinterpret_cast<float4*>(&As[r][c4 * 4]) = v;
        }
    }
    for (int cb = 0; cb < HEADS; cb++) {
        __syncthreads();
        #pragma unroll
        for (int i = 0; i < 16; i++) {
            int idx = threadIdx.x + i * 256;
            int r = idx >> 5, c = idx & 31;
            Bst[c][r] = B[(size_t)r * F1 + cb * 32 + c];
        }
        __syncthreads();
        unsigned long long acc2[8];
        #pragma unroll
        for (int r = 0; r < 8; r++) acc2[r] = 0ull;
        #pragma unroll 4
        for (int k2 = 0; k2 < IN_F / 2; k2++) {
            unsigned long long bv = *reinterpret_cast<const unsigned long long*>(&Bst[tx][k2 * 2]);
            #pragma unroll
            for (int r = 0; r < 8; r++) {
                unsigned long long av =
                    *reinterpret_cast<const unsigned long long*>(&As[ty * 8 + r][k2 * 2]);
                acc2[r] = fma2(av, bv, acc2[r]);
            }
        }
        float asv = as1[cb * HID + tx];
        float adv = ad1[cb * HID + tx];
        #pragma unroll
        for (int r = 0; r < 8; r++) {
            float acc = pairsum(acc2[r]);
            int gr = row0 + ty * 8 + r;
            if (gr < NN) g_h1h[(size_t)gr * F1 + cb * 32 + tx] = __float2half_rn(acc);
            float sv = acc * asv;
            float dv = acc * adv;
            #pragma unroll
            for (int o = 16; o; o >>= 1) {
                sv += __shfl_xor_sync(0xffffffffu, sv, o);
                dv += __shfl_xor_sync(0xffffffffu, dv, o);
            }
            if (tx == 0 && gr < NN) {
                g_asrc1[gr * HEADS + cb] = sv;
                g_adst1[gr * HEADS + cb] = dv;
            }
        }
    }
}

// ---------------- aggregate layer 1 (fp16 gather) ----------------
__global__ void aggregate1(const float* __restrict__ b1) {
    int n = (blockIdx.x * blockDim.x + threadIdx.x) >> 5;
    if (n >= NN) return;
    int lane = threadIdx.x & 31;
    int beg = g_rowstart[n];
    int end = beg + g_count[n] + 1;
    int h4 = lane & 3;
    float adst = (lane < 16) ? g_adst1[n * HEADS + h4] : 0.f;
    float denp = 0.f;
    float4 acc = make_float4(0.f, 0.f, 0.f, 0.f);
    int hh = lane >> 3;
    int j = beg;
    for (; j + 4 <= end; j += 4) {
        int sK = (lane < 4) ? __float_as_int(g_sb[j + lane].y) : 0;
        int s0 = __shfl_sync(0xffffffffu, sK, 0);
        int s1 = __shfl_sync(0xffffffffu, sK, 1);
        int s2 = __shfl_sync(0xffffffffu, sK, 2);
        int s3 = __shfl_sync(0xffffffffu, sK, 3);
        float ex = 0.f;
        if (lane < 16) {
            int k = lane >> 2;
            int sk = (k == 0) ? s0 : (k == 1) ? s1 : (k == 2) ? s2 : s3;
            float aed = ((const float*)&g_saed1[j + k])[h4];
            float lg = g_asrc1[sk * HEADS + h4] + adst + aed;
            lg = (lg > 0.f) ? lg : NEG_SLOPE * lg;
            ex = __expf(lg);
            denp += ex;
        }
        float e0 = __shfl_sync(0xffffffffu, ex, hh);
        float e1 = __shfl_sync(0xffffffffu, ex, 4 + hh);
        float e2 = __shfl_sync(0xffffffffu, ex, 8 + hh);
        float e3 = __shfl_sync(0xffffffffu, ex, 12 + hh);
        float4 v0 = gather_h4(&g_h1h[(size_t)s0 * F1 + lane * 4]);
        float4 v1 = gather_h4(&g_h1h[(size_t)s1 * F1 + lane * 4]);
        float4 v2 = gather_h4(&g_h1h[(size_t)s2 * F1 + lane * 4]);
        float4 v3 = gather_h4(&g_h1h[(size_t)s3 * F1 + lane * 4]);
        acc.x += e0 * v0.x + e1 * v1.x + e2 * v2.x + e3 * v3.x;
        acc.y += e0 * v0.y + e1 * v1.y + e2 * v2.y + e3 * v3.y;
        acc.z += e0 * v0.z + e1 * v1.z + e2 * v2.z + e3 * v3.z;
        acc.w += e0 * v0.w + e1 * v1.w + e2 * v2.w + e3 * v3.w;
    }
    for (; j < end; j++) {
        float2 sb = g_sb[j];
        int se = __float_as_int(sb.y);
        float ex = 0.f;
        if (lane < 4) {
            float aed = ((const float*)&g_saed1[j])[lane];
            float lg = g_asrc1[se * HEADS + lane] + adst + aed;
            lg = (lg > 0.f) ? lg : NEG_SLOPE * lg;
            ex = __expf(lg);
            denp += ex;
        }
        float eb = __shfl_sync(0xffffffffu, ex, hh);
        float4 v = gather_h4(&g_h1h[(size_t)se * F1 + lane * 4]);
        acc.x += eb * v.x;
        acc.y += eb * v.y;
        acc.z += eb * v.z;
        acc.w += eb * v.w;
    }
    float den = __shfl_sync(0xffffffffu, denp, hh)
              + __shfl_sync(0xffffffffu, denp, 4 + hh)
              + __shfl_sync(0xffffffffu, denp, 8 + hh)
              + __shfl_sync(0xffffffffu, denp, 12 + hh);
    float inv = 1.f / (den + 1e-16f);
    float4 bv = *reinterpret_cast<const float4*>(&b1[lane * 4]);
    float4 o;
    o.x = fmaxf(acc.x * inv + bv.x, 0.f);
    o.y = fmaxf(acc.y * inv + bv.y, 0.f);
    o.z = fmaxf(acc.z * inv + bv.z, 0.f);
    o.w = fmaxf(acc.w * inv + bv.w, 0.f);
    *reinterpret_cast<float4*>(&g_hr[(size_t)n * F1 + lane * 4]) = o;
}

// ---------------- GEMM2 (FFMA2): h2 = hr @ W2, fused coef2 ----------------
__global__ void gemm2(const float* __restrict__ B,
                      const float* __restrict__ as2, const float* __restrict__ ad2) {
    __shared__ float As[64][F1 + 4];
    __shared__ float Bst[32][F1 + 4];
    int row0 = blockIdx.x * 64;
    int tx = threadIdx.x & 31;
    int ty = threadIdx.x >> 5;
    {
        const float4* A4 = reinterpret_cast<const float4*>(g_hr);
        #pragma unroll
        for (int i = 0; i < 8; i++) {
            int idx = threadIdx.x + i * 256;
            int r = idx >> 5, c4 = idx & 31;
            int gr = row0 + r;
            float4 v = (gr < NN) ? A4[(size_t)gr * 32 + c4] : make_float4(0.f, 0.f, 0.f, 0.f);
            *reinterpret_cast<float4*>(&As[r][c4 * 4]) = v;
        }
    }
    #pragma unroll
    for (int i = 0; i < 16; i++) {
        int idx = threadIdx.x + i * 256;
        int r = idx >> 5, c = idx & 31;
        Bst[c][r] = B[(size_t)r * OUTF + c];
    }
    __syncthreads();
    unsigned long long acc2[8];
    #pragma unroll
    for (int r = 0; r < 8; r++) acc2[r] = 0ull;
    #pragma unroll 4
    for (int k2 = 0; k2 < F1 / 2; k2++) {
        unsigned long long bv = *reinterpret_cast<const unsigned long long*>(&Bst[tx][k2 * 2]);
        #pragma unroll
        for (int r = 0; r < 8; r++) {
            unsigned long long av =
                *reinterpret_cast<const unsigned long long*>(&As[ty * 8 + r][k2 * 2]);
            acc2[r] = fma2(av, bv, acc2[r]);
        }
    }
    float asv = as2[tx];
    float adv = ad2[tx];
    #pragma unroll
    for (int r = 0; r < 8; r++) {
        float acc = pairsum(acc2[r]);
        int gr = row0 + ty * 8 + r;
        if (gr < NN) g_h2[(size_t)gr * OUTF + tx] = acc;
        float sv = acc * asv;
        float dv = acc * adv;
        #pragma unroll
        for (int o = 16; o; o >>= 1) {
            sv += __shfl_xor_sync(0xffffffffu, sv, o);
            dv += __shfl_xor_sync(0xffffffffu, dv, o);
        }
        if (tx == 0 && gr < NN) {
            g_asrc2[gr] = sv;
            g_adst2[gr] = dv;
        }
    }
}

// ---------------- aggregate layer 2 ----------------
__global__ void aggregate2(float* __restrict__ out, const float* __restrict__ b2) {
    int n = (blockIdx.x * blockDim.x + threadIdx.x) >> 5;
    if (n >= NN) return;
    int lane = threadIdx.x & 31;
    int beg = g_rowstart[n];
    int end = beg + g_count[n] + 1;
    float adst = g_adst2[n];
    float denp = 0.f, acc = 0.f;
    int j = beg;
    for (; j + 4 <= end; j += 4) {
        int sK = 0;
        float ex = 0.f;
        if (lane < 4) {
            float2 sbv = g_sb[j + lane];
            sK = __float_as_int(sbv.y);
            float lg = g_asrc2[sK] + adst + sbv.x;
            lg = (lg > 0.f) ? lg : NEG_SLOPE * lg;
            ex = __expf(lg);
            denp += ex;
        }
        int s0 = __shfl_sync(0xffffffffu, sK, 0);
        int s1 = __shfl_sync(0xffffffffu, sK, 1);
        int s2 = __shfl_sync(0xffffffffu, sK, 2);
        int s3 = __shfl_sync(0xffffffffu, sK, 3);
        float e0 = __shfl_sync(0xffffffffu, ex, 0);
        float e1 = __shfl_sync(0xffffffffu, ex, 1);
        float e2 = __shfl_sync(0xffffffffu, ex, 2);
        float e3 = __shfl_sync(0xffffffffu, ex, 3);
        acc += e0 * g_h2[(size_t)s0 * OUTF + lane]
             + e1 * g_h2[(size_t)s1 * OUTF + lane]
             + e2 * g_h2[(size_t)s2 * OUTF + lane]
             + e3 * g_h2[(size_t)s3 * OUTF + lane];
    }
    for (; j < end; j++) {
        float2 sb = g_sb[j];
        int se = __float_as_int(sb.y);
        float ex = 0.f;
        if (lane == 0) {
            float lg = g_asrc2[se] + adst + sb.x;
            lg = (lg > 0.f) ? lg : NEG_SLOPE * lg;
            ex = __expf(lg);
            denp += ex;
        }
        float eb = __shfl_sync(0xffffffffu, ex, 0);
        acc += eb * g_h2[(size_t)se * OUTF + lane];
    }
    float den = __shfl_sync(0xffffffffu, denp, 0)
              + __shfl_sync(0xffffffffu, denp, 1)
              + __shfl_sync(0xffffffffu, denp, 2)
              + __shfl_sync(0xffffffffu, denp, 3);
    out[(size_t)n * OUTF + lane] = acc / (den + 1e-16f) + b2[lane];
}

// ---------------- launch ----------------
extern "C" void kernel_launch(void* const* d_in, const int* in_sizes, int n_in,
                              void* d_out, int out_size) {
    int used[64];
    for (int i = 0; i < n_in && i < 64; i++) used[i] = 0;
    auto take = [&](int want) -> const void* {
        for (int i = 0; i < n_in && i < 64; i++)
            if (!used[i] && in_sizes[i] == want) { used[i] = 1; return d_in[i]; }
        return nullptr;
    };
    const float* x   = (const float*)take(NN * IN_F);
    const void*  eix = take(2 * EE);
    const float* ea  = (const float*)take(EE * ED_F);
    const float* W1  = (const float*)take(IN_F * F1);
    const float* We1 = (const float*)take(ED_F * F1);
    const float* W2  = (const float*)take(F1 * OUTF);
    const float* We2 = (const float*)take(ED_F * OUTF);
    const float* g128[4] = {nullptr, nullptr, nullptr, nullptr};
    const float* g32[4]  = {nullptr, nullptr, nullptr, nullptr};
    int n128 = 0, n32 = 0;
    for (int i = 0; i < n_in && i < 64; i++) {
        if (used[i]) continue;
        if (in_sizes[i] == 128 && n128 < 4) g128[n128++] = (const float*)d_in[i];
        else if (in_sizes[i] == 32 && n32 < 4) g32[n32++] = (const float*)d_in[i];
    }
    const float* as1 = g128[0], *ad1 = g128[1], *ae1 = g128[2], *b1 = g128[3];
    const float* as2 = g32[0],  *ad2 = g32[1],  *ae2 = g32[2],  *b2 = g32[3];
    if (!x || !eix || !ea || !W1 || !We1 || !W2 || !We2 || n128 < 4 || n32 < 4) {
        x   = (const float*)d_in[0];  eix = d_in[1];               ea  = (const float*)d_in[2];
        W1  = (const float*)d_in[3];  We1 = (const float*)d_in[4];
        as1 = (const float*)d_in[5];  ad1 = (const float*)d_in[6]; ae1 = (const float*)d_in[7];
        b1  = (const float*)d_in[8];  W2  = (const float*)d_in[9]; We2 = (const float*)d_in[10];
        as2 = (const float*)d_in[11]; ad2 = (const float*)d_in[12]; ae2 = (const float*)d_in[13];
        b2  = (const float*)d_in[14];
    }
    float* out = (float*)d_out;

    const int TB = 256;

    setup<<<(NN + TB - 1) / TB, TB>>>(eix, We1, ae1, We2, ae2);
    count_edges<<<(EE + TB * 4 - 1) / (TB * 4), TB>>>(eix);
    assign_rows<<<(NN + TB - 1) / TB, TB>>>();
    edge_dots_scatter<<<(EE + TB - 1) / TB, TB>>>(eix, ea);
    selfloop_fill<<<(NN + TB - 1) / TB, TB>>>();

    gemm1<<<(NN + 63) / 64, TB>>>(x, W1, as1, ad1);
    aggregate1<<<(int)(((size_t)NN * 32 + TB - 1) / TB), TB>>>(b1);

    gemm2<<<(NN + 63) / 64, TB>>>(W2, as2, ad2);
    aggregate2<<<(int)(((size_t)NN * 32 + TB - 1) / TB), TB>>>(out, b2);
}